// round 1
// baseline (speedup 1.0000x reference)
#include <cuda_runtime.h>
#include <math.h>

#define BB 8
#define IN_N 8
#define JJ 8
#define SS 187
#define FF 64
#define OO 64
#define CC 67
#define KK 15
#define EE 256
#define SF (SS*FF)
#define NOUT (BB*JJ*SS*OO)   // 765952

// ---------------- device scratch (no allocations allowed) ----------------
__device__ unsigned int g_maxbits;
__device__ float g_act [BB*IN_N*JJ*SS*FF];   // 6,127,616 floats
__device__ float g_mask[BB*IN_N*JJ];
__device__ float g_gate[BB*IN_N*JJ];
__device__ float g_comb[BB*JJ*SS*FF];
__device__ float g_xp  [BB*JJ*SS*OO];
__device__ float g_kt  [BB*JJ*SS*EE];
__device__ float g_qt  [BB*JJ*SS*EE];
__device__ float g_raw [BB*JJ*SS*SS];

// ---------------- K0: reset ----------------
__global__ void k_reset() { g_maxbits = 0u; }

// ---------------- K1: global max|x| ----------------
__global__ void k_maxabs(const float* __restrict__ x, int n) {
    __shared__ unsigned int sred[256];
    unsigned int m = 0u;
    for (int i = blockIdx.x * blockDim.x + threadIdx.x; i < n; i += gridDim.x * blockDim.x) {
        unsigned int b = __float_as_uint(fabsf(x[i]));
        m = max(m, b);
    }
    sred[threadIdx.x] = m;
    __syncthreads();
    for (int st = 128; st > 0; st >>= 1) {
        if (threadIdx.x < st) sred[threadIdx.x] = max(sred[threadIdx.x], sred[threadIdx.x + st]);
        __syncthreads();
    }
    if (threadIdx.x == 0) atomicMax(&g_maxbits, sred[0]);
}

// ---------------- K2: sparse spline -> activated, energies -> mask/gate ----------------
__global__ void k_spline(const float* __restrict__ x_in,
                         const float* __restrict__ sw,     // [IN,J,C]
                         const float* __restrict__ tau,    // [IN,J]
                         const float* __restrict__ temp,   // scalar
                         const float* __restrict__ omiga)  // [IN,J]
{
    int bi = blockIdx.x;           // b*IN + i
    int i  = bi % IN_N;
    __shared__ float s_sw[JJ*CC];
    __shared__ float s_om[JJ];
    __shared__ float s_red[8][9];  // [warp][j]
    for (int t = threadIdx.x; t < JJ*CC; t += blockDim.x) s_sw[t] = sw[i*JJ*CC + t];
    if (threadIdx.x < JJ) s_om[threadIdx.x] = fabsf(omiga[i*JJ + threadIdx.x]);
    __syncthreads();

    float maxv = __uint_as_float(g_maxbits) + 1e-8f;
    float inv_maxv_sc = 0.95f / maxv;
    const float invh = (float)(CC - 1) * 0.5f;   // 1/h, h = 2/(C-1)

    float acc[JJ];
#pragma unroll
    for (int j = 0; j < JJ; j++) acc[j] = 0.f;

    const float* xb   = x_in + (size_t)bi * SF;
    float*       actb = g_act + (size_t)bi * JJ * SF;

    for (int idx = threadIdx.x; idx < SF; idx += blockDim.x) {
        float x  = xb[idx];
        float xn = x * inv_maxv_sc;
        xn = fminf(fmaxf(xn, -0.99f), 0.99f);
        float u = (xn + 1.0f) * invh;
        int c0 = (int)floorf(u) - 1;
        float bas[4]; int cs[4];
#pragma unroll
        for (int k = 0; k < 4; k++) {
            int c = c0 + k;
            float d  = fabsf(u - (float)c);
            float r2 = fmaxf(2.0f - d, 0.f);
            float r1 = fmaxf(1.0f - d, 0.f);
            float v  = r2*r2*r2*(1.0f/6.0f) - r1*r1*r1*(4.0f/6.0f);
            bas[k] = (c >= 0 && c < CC) ? v : 0.f;
            cs[k]  = min(max(c, 0), CC - 1);
        }
#pragma unroll
        for (int j = 0; j < JJ; j++) {
            const float* swj = s_sw + j*CC;
            float sm = bas[0]*swj[cs[0]] + bas[1]*swj[cs[1]]
                     + bas[2]*swj[cs[2]] + bas[3]*swj[cs[3]];
            float a = sm + s_om[j] * x;
            actb[j*SF + idx] = a;
            acc[j] += a * a;
        }
    }

    int lane = threadIdx.x & 31, wid = threadIdx.x >> 5;
#pragma unroll
    for (int j = 0; j < JJ; j++) {
#pragma unroll
        for (int o = 16; o > 0; o >>= 1) acc[j] += __shfl_down_sync(0xffffffffu, acc[j], o);
        if (lane == 0) s_red[wid][j] = acc[j];
    }
    __syncthreads();
    if (threadIdx.x < JJ) {
        int j = threadIdx.x;
        float e = 0.f;
#pragma unroll
        for (int w = 0; w < 8; w++) e += s_red[w][j];
        e *= (1.0f / (float)SF);
        float sq = sqrtf(e + 1e-8f);
        float ta = fabsf(tau[i*JJ + j]);
        float tv = fabsf(temp[0]) * sqrtf((float)SS / 256.0f) + 1e-4f;
        float mk = 1.0f / (1.0f + expf(-(sq - ta) / tv));
        float mult = sq / (ta + 1e-8f);
        g_mask[bi*JJ + j] = mk;
        g_gate[bi*JJ + j] = mult * mk;
    }
}

// ---------------- K3: combined -> LN -> x_prime ----------------
__global__ void k_comb_xp(const float* __restrict__ W2,      // [J,F,O]
                          const float* __restrict__ bparam,  // [J,S,O]
                          const float* __restrict__ lnsc,    // [J,F]
                          const float* __restrict__ lnbi)    // [J,F]
{
    int id = blockIdx.x;              // (b*J + j)*S + s
    int s  = id % SS;
    int bj = id / SS;
    int j  = bj % JJ;
    int b  = bj / JJ;
    int f  = threadIdx.x;

    float c = 0.f;
#pragma unroll
    for (int i = 0; i < IN_N; i++) {
        int bij = (b*IN_N + i)*JJ + j;
        c += g_act[(((size_t)(b*IN_N + i)*JJ + j)*SS + s)*FF + f] * g_mask[bij];
    }
    g_comb[((size_t)bj*SS + s)*FF + f] = c;

    __shared__ float sh[64];
    __shared__ float s_xln[64];
    sh[f] = c; __syncthreads();
    for (int st = 32; st > 0; st >>= 1) { if (f < st) sh[f] += sh[f + st]; __syncthreads(); }
    float mean = sh[0] * (1.0f/64.0f);
    __syncthreads();
    float d = c - mean;
    sh[f] = d * d; __syncthreads();
    for (int st = 32; st > 0; st >>= 1) { if (f < st) sh[f] += sh[f + st]; __syncthreads(); }
    float rstd = rsqrtf(sh[0] * (1.0f/64.0f) + 1e-5f);
    s_xln[f] = d * rstd * lnsc[j*FF + f] + lnbi[j*FF + f];
    __syncthreads();

    int o = f;
    float acc = bparam[(j*SS + s)*OO + o];
    const float* w2j = W2 + (size_t)j*FF*OO;
#pragma unroll
    for (int ff = 0; ff < FF; ff++) acc += s_xln[ff] * w2j[ff*OO + o];
    g_xp[((size_t)bj*SS + s)*OO + o] = acc;
}

// ---------------- K4: build Kt/Qt and LayerNorm over 256 ----------------
__global__ void k_ktqt(const float* __restrict__ proj) {
    int id = blockIdx.x;
    int s  = id % SS;
    int bj = id / SS;
    int j  = bj % JJ;
    int b  = bj / JJ;
    int t  = threadIdx.x;         // 0..255
    int m  = t >> 6, d = t & 63;
    int iK = 2*m, iQ = 2*m + 1;

    float kv = proj[(((size_t)(b*IN_N + iK))*SS + s)*FF + d] * g_gate[(b*IN_N + iK)*JJ + j];
    float qv = proj[(((size_t)(b*IN_N + iQ))*SS + s)*FF + d] * g_gate[(b*IN_N + iQ)*JJ + j];

    __shared__ float4 red4[256];
    red4[t] = make_float4(kv, kv*kv, qv, qv*qv);
    __syncthreads();
    for (int st = 128; st > 0; st >>= 1) {
        if (t < st) {
            float4 a = red4[t], c = red4[t + st];
            a.x += c.x; a.y += c.y; a.z += c.z; a.w += c.w;
            red4[t] = a;
        }
        __syncthreads();
    }
    float4 tot = red4[0];
    float km = tot.x * (1.0f/256.0f);
    float kv2 = tot.y * (1.0f/256.0f) - km*km;
    float qm = tot.z * (1.0f/256.0f);
    float qv2 = tot.w * (1.0f/256.0f) - qm*qm;
    float kr = rsqrtf(kv2 + 1e-5f);
    float qr = rsqrtf(qv2 + 1e-5f);

    size_t base = ((size_t)bj*SS + s)*EE + t;
    g_kt[base] = (kv - km) * kr;
    g_qt[base] = (qv - qm) * qr;
}

// ---------------- K5: raw = Ktn @ Qtn^T (NT GEMM, 64x64x16 tiles) ----------------
__global__ void k_gemm() {
    int bj = blockIdx.z;
    const float* A  = g_kt + (size_t)bj*SS*EE;
    const float* Bm = g_qt + (size_t)bj*SS*EE;
    float*       Cm = g_raw + (size_t)bj*SS*SS;
    int m0 = blockIdx.y * 64, n0 = blockIdx.x * 64;

    __shared__ float As[16][64];
    __shared__ float Bs[16][64];

    int tid = threadIdx.x;
    int lr  = tid >> 2;          // 0..63 row within tile
    int lc  = (tid & 3) * 4;     // k offset (float4)
    int ty  = tid >> 4, tx = tid & 15;

    float acc[4][4];
#pragma unroll
    for (int r = 0; r < 4; r++)
#pragma unroll
        for (int c = 0; c < 4; c++) acc[r][c] = 0.f;

    for (int k0 = 0; k0 < EE; k0 += 16) {
        int row = m0 + lr;
        float4 va = (row < SS) ? *(const float4*)(A + (size_t)row*EE + k0 + lc)
                               : make_float4(0,0,0,0);
        As[lc+0][lr] = va.x; As[lc+1][lr] = va.y; As[lc+2][lr] = va.z; As[lc+3][lr] = va.w;
        int rowb = n0 + lr;
        float4 vb = (rowb < SS) ? *(const float4*)(Bm + (size_t)rowb*EE + k0 + lc)
                                : make_float4(0,0,0,0);
        Bs[lc+0][lr] = vb.x; Bs[lc+1][lr] = vb.y; Bs[lc+2][lr] = vb.z; Bs[lc+3][lr] = vb.w;
        __syncthreads();
#pragma unroll
        for (int k = 0; k < 16; k++) {
            float a[4], bb[4];
#pragma unroll
            for (int r = 0; r < 4; r++) a[r]  = As[k][ty*4 + r];
#pragma unroll
            for (int c = 0; c < 4; c++) bb[c] = Bs[k][tx*4 + c];
#pragma unroll
            for (int r = 0; r < 4; r++)
#pragma unroll
                for (int c = 0; c < 4; c++) acc[r][c] += a[r] * bb[c];
        }
        __syncthreads();
    }
#pragma unroll
    for (int r = 0; r < 4; r++) {
        int sRow = m0 + ty*4 + r;
        if (sRow < SS) {
#pragma unroll
            for (int c = 0; c < 4; c++) {
                int tCol = n0 + tx*4 + c;
                if (tCol < SS) Cm[(size_t)sRow*SS + tCol] = acc[r][c];
            }
        }
    }
}

// ---------------- K6: softmax + attn@xp + |alpha|I + conv + residual ----------------
__global__ void k_epi(const float* __restrict__ w3,      // [J,O,KS]
                      const float* __restrict__ alpha,
                      const float* __restrict__ beta,
                      const float* __restrict__ theta,
                      const float* __restrict__ gamma,
                      const float* __restrict__ temp,
                      float* __restrict__ outp) {
    extern __shared__ float smem[];
    float* xp_s = smem;                 // SS*OO = 11968
    float* w3_s = xp_s + SS*OO;         // OO*KK = 960
    float* wrow = w3_s + OO*KK;         // 192
    float* red  = wrow + 192;           // 256

    int bj = blockIdx.x;
    int j  = bj % JJ;
    int tid = threadIdx.x;

    const float* xpb = g_xp + (size_t)bj*SS*OO;
    for (int t = tid; t < SS*OO; t += 256) xp_s[t] = xpb[t];
    for (int t = tid; t < OO*KK; t += 256) w3_s[t] = w3[(size_t)j*OO*KK + t];

    float tv = fabsf(temp[0]) * sqrtf((float)SS / 256.0f) + 1e-4f;
    float inv_scale = 1.0f / (16.0f * tv);
    float al = fabsf(alpha[j]), be = fabsf(beta[j]);
    float th = fabsf(theta[j]), ga = gamma[j];
    __syncthreads();

    int s0 = blockIdx.y * 47;
    int s1 = min(SS, s0 + 47);
    const float* rawb  = g_raw  + (size_t)bj*SS*SS;
    const float* combb = g_comb + (size_t)bj*SS*OO;
    float*       outb  = outp   + (size_t)bj*SS*OO;
    int o = tid & 63, part = tid >> 6;

    for (int s = s0; s < s1; s++) {
        float z = (tid < SS) ? rawb[(size_t)s*SS + tid] * inv_scale : -3.0e38f;
        red[tid] = z; __syncthreads();
        for (int st = 128; st > 0; st >>= 1) {
            if (tid < st) red[tid] = fmaxf(red[tid], red[tid + st]);
            __syncthreads();
        }
        float mx = red[0]; __syncthreads();
        float e = (tid < SS) ? expf(z - mx) : 0.f;
        red[tid] = e; __syncthreads();
        for (int st = 128; st > 0; st >>= 1) {
            if (tid < st) red[tid] += red[tid + st];
            __syncthreads();
        }
        float inv = 1.0f / red[0];
        __syncthreads();
        if (tid < SS) wrow[tid] = e * inv;
        __syncthreads();

        float acc = 0.f;
        for (int t = part; t < SS; t += 4) acc += wrow[t] * xp_s[t*OO + o];
        red[tid] = acc; __syncthreads();
        if (part == 0) {
            float sum = red[o] + red[64 + o] + red[128 + o] + red[192 + o];
            float cv = 0.f;
#pragma unroll
            for (int k = 0; k < KK; k++) {
                int ssi = s + k - 7;
                if (ssi >= 0 && ssi < SS) cv += xp_s[ssi*OO + o] * w3_s[o*KK + k];
            }
            outb[(size_t)s*OO + o] = be*sum + al*xp_s[s*OO + o] + th*cv + ga*combb[(size_t)s*OO + o];
        }
        __syncthreads();
    }
}

// ---------------- launch ----------------
extern "C" void kernel_launch(void* const* d_in, const int* in_sizes, int n_in,
                              void* d_out, int out_size) {
    const float* x_in   = (const float*)d_in[0];
    const float* proj   = (const float*)d_in[1];
    const float* sw     = (const float*)d_in[2];
    const float* tau    = (const float*)d_in[3];
    const float* temp   = (const float*)d_in[4];
    const float* omiga  = (const float*)d_in[5];
    const float* W2     = (const float*)d_in[6];
    const float* bparam = (const float*)d_in[7];
    const float* lnsc   = (const float*)d_in[8];
    const float* lnbi   = (const float*)d_in[9];
    const float* alpha  = (const float*)d_in[10];
    const float* beta   = (const float*)d_in[11];
    const float* theta  = (const float*)d_in[12];
    const float* gamma  = (const float*)d_in[13];
    const float* w3     = (const float*)d_in[14];
    float* outp = (float*)d_out;

    static const size_t epi_smem = (size_t)(SS*OO + OO*KK + 192 + 256) * sizeof(float);
    cudaFuncSetAttribute(k_epi, cudaFuncAttributeMaxDynamicSharedMemorySize, (int)epi_smem);

    k_reset<<<1, 1>>>();
    k_maxabs<<<256, 256>>>(x_in, BB*IN_N*SS*FF);
    k_spline<<<BB*IN_N, 256>>>(x_in, sw, tau, temp, omiga);
    k_comb_xp<<<BB*JJ*SS, 64>>>(W2, bparam, lnsc, lnbi);
    k_ktqt<<<BB*JJ*SS, 256>>>(proj);
    k_gemm<<<dim3(3, 3, BB*JJ), 256>>>();
    k_epi<<<dim3(BB*JJ, 4), 256, epi_smem>>>(w3, alpha, beta, theta, gamma, temp, outp);

    // second tuple output: x_prime, if the harness expects it concatenated
    if (out_size >= 2 * NOUT) {
        void* xp_dev = nullptr;
        cudaGetSymbolAddress(&xp_dev, g_xp);
        cudaMemcpyAsync((float*)d_out + NOUT, xp_dev, (size_t)NOUT * sizeof(float),
                        cudaMemcpyDeviceToDevice);
    }
}

// round 2
// speedup vs baseline: 1.5027x; 1.5027x over previous
#include <cuda_runtime.h>
#include <math.h>

#define BB 8
#define IN_N 8
#define JJ 8
#define SS 187
#define FF 64
#define OO 64
#define CC 67
#define KK 15
#define EE 256
#define SF (SS*FF)
#define NOUT (BB*JJ*SS*OO)   // 765952

// ---------------- device scratch ----------------
__device__ unsigned int g_maxbits;
__device__ float g_energy[BB*IN_N*JJ];
__device__ float g_mask[BB*IN_N*JJ];
__device__ float g_gate[BB*IN_N*JJ];
__device__ float g_comb[BB*JJ*SS*FF];
__device__ float g_xp  [BB*JJ*SS*OO];
__device__ float g_kt  [BB*JJ*SS*EE];
__device__ float g_qt  [BB*JJ*SS*EE];
__device__ float g_raw [BB*JJ*SS*SS];

// ---------------- K0: reset maxbits + energies ----------------
__global__ void k_reset() {
    int t = blockIdx.x * blockDim.x + threadIdx.x;
    if (t == 0) g_maxbits = 0u;
    if (t < BB*IN_N*JJ) g_energy[t] = 0.f;
}

// ---------------- K1: global max|x| ----------------
__global__ void k_maxabs(const float* __restrict__ x, int n) {
    __shared__ unsigned int sred[256];
    unsigned int m = 0u;
    for (int i = blockIdx.x * blockDim.x + threadIdx.x; i < n; i += gridDim.x * blockDim.x) {
        m = max(m, __float_as_uint(fabsf(x[i])));
    }
    sred[threadIdx.x] = m;
    __syncthreads();
    for (int st = 128; st > 0; st >>= 1) {
        if (threadIdx.x < st) sred[threadIdx.x] = max(sred[threadIdx.x], sred[threadIdx.x + st]);
        __syncthreads();
    }
    if (threadIdx.x == 0) atomicMax(&g_maxbits, sred[0]);
}

// ---------------- spline basis helper ----------------
__device__ __forceinline__ void spline_basis(float x, float inv_maxv_sc, float invh,
                                             float bas[4], int cs[4]) {
    float xn = x * inv_maxv_sc;
    xn = fminf(fmaxf(xn, -0.99f), 0.99f);
    float u = (xn + 1.0f) * invh;
    int c0 = (int)floorf(u) - 1;
#pragma unroll
    for (int k = 0; k < 4; k++) {
        int c = c0 + k;
        float d  = fabsf(u - (float)c);
        float r2 = fmaxf(2.0f - d, 0.f);
        float r1 = fmaxf(1.0f - d, 0.f);
        float v  = r2*r2*r2*(1.0f/6.0f) - r1*r1*r1*(4.0f/6.0f);
        bas[k] = (c >= 0 && c < CC) ? v : 0.f;
        cs[k]  = min(max(c, 0), CC - 1);
    }
}

// ---------------- K2a: energy pass (no act store) ----------------
#define ECHUNK 1496   // SF/8
__global__ void k_energy(const float* __restrict__ x_in,
                         const float* __restrict__ sw,
                         const float* __restrict__ omiga) {
    int bi = blockIdx.x;           // b*IN + i
    int i  = bi % IN_N;
    __shared__ float s_sw[JJ*CC];
    __shared__ float s_om[JJ];
    __shared__ float s_red[8][9];
    for (int t = threadIdx.x; t < JJ*CC; t += blockDim.x) s_sw[t] = sw[i*JJ*CC + t];
    if (threadIdx.x < JJ) s_om[threadIdx.x] = fabsf(omiga[i*JJ + threadIdx.x]);
    __syncthreads();

    float maxv = __uint_as_float(g_maxbits) + 1e-8f;
    float inv_maxv_sc = 0.95f / maxv;
    const float invh = (float)(CC - 1) * 0.5f;

    float acc[JJ];
#pragma unroll
    for (int j = 0; j < JJ; j++) acc[j] = 0.f;

    const float* xb = x_in + (size_t)bi * SF;
    int start = blockIdx.y * ECHUNK;
    int end   = min(SF, start + ECHUNK);
    for (int idx = start + threadIdx.x; idx < end; idx += blockDim.x) {
        float x = xb[idx];
        float bas[4]; int cs[4];
        spline_basis(x, inv_maxv_sc, invh, bas, cs);
#pragma unroll
        for (int j = 0; j < JJ; j++) {
            const float* swj = s_sw + j*CC;
            float a = bas[0]*swj[cs[0]] + bas[1]*swj[cs[1]]
                    + bas[2]*swj[cs[2]] + bas[3]*swj[cs[3]] + s_om[j] * x;
            acc[j] += a * a;
        }
    }
    int lane = threadIdx.x & 31, wid = threadIdx.x >> 5;
#pragma unroll
    for (int j = 0; j < JJ; j++) {
#pragma unroll
        for (int o = 16; o > 0; o >>= 1) acc[j] += __shfl_down_sync(0xffffffffu, acc[j], o);
        if (lane == 0) s_red[wid][j] = acc[j];
    }
    __syncthreads();
    if (threadIdx.x < JJ) {
        int j = threadIdx.x;
        float e = 0.f;
#pragma unroll
        for (int w = 0; w < 8; w++) e += s_red[w][j];
        atomicAdd(&g_energy[bi*JJ + j], e);
    }
}

// ---------------- K2b: mask/gate ----------------
__global__ void k_maskgate(const float* __restrict__ tau, const float* __restrict__ temp) {
    int t = blockIdx.x * blockDim.x + threadIdx.x;
    if (t >= BB*IN_N*JJ) return;
    int j = t & 7;
    int i = (t >> 3) % IN_N;
    float e = g_energy[t] * (1.0f / (float)SF);
    float sq = sqrtf(e + 1e-8f);
    float ta = fabsf(tau[i*JJ + j]);
    float tv = fabsf(temp[0]) * sqrtf((float)SS / 256.0f) + 1e-4f;
    float mk = 1.0f / (1.0f + expf(-(sq - ta) / tv));
    g_mask[t] = mk;
    g_gate[t] = (sq / (ta + 1e-8f)) * mk;
}

// ---------------- K3: combined pass (recompute spline, masks folded in) ----------------
__global__ void k_combined(const float* __restrict__ x_in,
                           const float* __restrict__ sw,
                           const float* __restrict__ omiga) {
    int b = blockIdx.x;
    __shared__ float s_sw[IN_N*JJ*CC];   // pre-multiplied by mask
    __shared__ float s_omk[IN_N][JJ];    // |omiga|*mask
    for (int t = threadIdx.x; t < IN_N*JJ*CC; t += blockDim.x) {
        int i = t / (JJ*CC);
        int j = (t / CC) % JJ;
        s_sw[t] = sw[t] * g_mask[(b*IN_N + i)*JJ + j];
    }
    if (threadIdx.x < IN_N*JJ) {
        int i = threadIdx.x >> 3, j = threadIdx.x & 7;
        s_omk[i][j] = fabsf(omiga[i*JJ + j]) * g_mask[(b*IN_N + i)*JJ + j];
    }
    __syncthreads();

    float maxv = __uint_as_float(g_maxbits) + 1e-8f;
    float inv_maxv_sc = 0.95f / maxv;
    const float invh = (float)(CC - 1) * 0.5f;

    int start = blockIdx.y * ECHUNK;
    int end   = min(SF, start + ECHUNK);
    const float* xb   = x_in + (size_t)b * IN_N * SF;
    float*       cmbb = g_comb + (size_t)b * JJ * SF;

    for (int idx = start + threadIdx.x; idx < end; idx += blockDim.x) {
        float acc[JJ];
#pragma unroll
        for (int j = 0; j < JJ; j++) acc[j] = 0.f;
#pragma unroll
        for (int i = 0; i < IN_N; i++) {
            float x = xb[(size_t)i*SF + idx];
            float bas[4]; int cs[4];
            spline_basis(x, inv_maxv_sc, invh, bas, cs);
            const float* swi = s_sw + i*JJ*CC;
#pragma unroll
            for (int j = 0; j < JJ; j++) {
                const float* swj = swi + j*CC;
                acc[j] += bas[0]*swj[cs[0]] + bas[1]*swj[cs[1]]
                        + bas[2]*swj[cs[2]] + bas[3]*swj[cs[3]] + s_omk[i][j] * x;
            }
        }
#pragma unroll
        for (int j = 0; j < JJ; j++) cmbb[(size_t)j*SF + idx] = acc[j];
    }
}

// ---------------- K4: combined -> LN -> x_prime (W2 in shared, 4 rows/iter) ----------------
__global__ void k_xp(const float* __restrict__ W2,
                     const float* __restrict__ bparam,
                     const float* __restrict__ lnsc,
                     const float* __restrict__ lnbi) {
    int bj = blockIdx.x;           // b*J + j
    int j  = bj % JJ;
    __shared__ float W2s[FF*OO];   // 16KB
    __shared__ float xlns[4][FF];
    __shared__ float sred[4][2][2];
    __shared__ float s_sc[FF], s_bi[FF];
    for (int t = threadIdx.x; t < FF*OO/4; t += blockDim.x)
        ((float4*)W2s)[t] = ((const float4*)(W2 + (size_t)j*FF*OO))[t];
    if (threadIdx.x < FF) {
        s_sc[threadIdx.x] = lnsc[j*FF + threadIdx.x];
        s_bi[threadIdx.x] = lnbi[j*FF + threadIdx.x];
    }
    __syncthreads();

    int tid = threadIdx.x;
    int r = tid >> 6, f = tid & 63;
    int lane = tid & 31, half = (tid >> 5) & 1;
    int s0 = blockIdx.y * 48;

    const float* cmb = g_comb + (size_t)bj*SS*FF;
    float*       xpb = g_xp   + (size_t)bj*SS*OO;

    for (int it = 0; it < 12; it++) {
        int s = s0 + it*4 + r;
        float c = (s < SS) ? cmb[(size_t)s*FF + f] : 0.f;
        float sm = c, sq = c*c;
#pragma unroll
        for (int o = 16; o > 0; o >>= 1) {
            sm += __shfl_down_sync(0xffffffffu, sm, o);
            sq += __shfl_down_sync(0xffffffffu, sq, o);
        }
        if (lane == 0) { sred[r][half][0] = sm; sred[r][half][1] = sq; }
        __syncthreads();
        float tsum = sred[r][0][0] + sred[r][1][0];
        float tsq  = sred[r][0][1] + sred[r][1][1];
        float mean = tsum * (1.0f/64.0f);
        float var  = tsq * (1.0f/64.0f) - mean*mean;
        float rstd = rsqrtf(var + 1e-5f);
        xlns[r][f] = (c - mean) * rstd * s_sc[f] + s_bi[f];
        __syncthreads();
        if (s < SS) {
            float acc = bparam[((size_t)j*SS + s)*OO + f];
#pragma unroll
            for (int ff = 0; ff < FF; ff++) acc += xlns[r][ff] * W2s[ff*OO + f];
            xpb[(size_t)s*OO + f] = acc;
        }
        __syncthreads();
    }
}

// ---------------- K5: build Kt/Qt + LN(256) ----------------
__global__ void k_ktqt(const float* __restrict__ proj) {
    int id = blockIdx.x;
    int s  = id % SS;
    int bj = id / SS;
    int j  = bj % JJ;
    int b  = bj / JJ;
    int t  = threadIdx.x;
    int m  = t >> 6, d = t & 63;
    int iK = 2*m, iQ = 2*m + 1;

    float kv = proj[(((size_t)(b*IN_N + iK))*SS + s)*FF + d] * g_gate[(b*IN_N + iK)*JJ + j];
    float qv = proj[(((size_t)(b*IN_N + iQ))*SS + s)*FF + d] * g_gate[(b*IN_N + iQ)*JJ + j];

    __shared__ float4 red4[256];
    red4[t] = make_float4(kv, kv*kv, qv, qv*qv);
    __syncthreads();
    for (int st = 128; st > 0; st >>= 1) {
        if (t < st) {
            float4 a = red4[t], c = red4[t + st];
            a.x += c.x; a.y += c.y; a.z += c.z; a.w += c.w;
            red4[t] = a;
        }
        __syncthreads();
    }
    float4 tot = red4[0];
    float km = tot.x * (1.0f/256.0f);
    float kvar = tot.y * (1.0f/256.0f) - km*km;
    float qm = tot.z * (1.0f/256.0f);
    float qvar = tot.w * (1.0f/256.0f) - qm*qm;
    size_t base = ((size_t)bj*SS + s)*EE + t;
    g_kt[base] = (kv - km) * rsqrtf(kvar + 1e-5f);
    g_qt[base] = (qv - qm) * rsqrtf(qvar + 1e-5f);
}

// ---------------- K6: raw = Ktn @ Qtn^T (NT GEMM) ----------------
__global__ void k_gemm() {
    int bj = blockIdx.z;
    const float* A  = g_kt + (size_t)bj*SS*EE;
    const float* Bm = g_qt + (size_t)bj*SS*EE;
    float*       Cm = g_raw + (size_t)bj*SS*SS;
    int m0 = blockIdx.y * 64, n0 = blockIdx.x * 64;

    __shared__ float As[16][64];
    __shared__ float Bs[16][64];
    int tid = threadIdx.x;
    int lr  = tid >> 2;
    int lc  = (tid & 3) * 4;
    int ty  = tid >> 4, tx = tid & 15;

    float acc[4][4];
#pragma unroll
    for (int r = 0; r < 4; r++)
#pragma unroll
        for (int c = 0; c < 4; c++) acc[r][c] = 0.f;

    for (int k0 = 0; k0 < EE; k0 += 16) {
        int row = m0 + lr;
        float4 va = (row < SS) ? *(const float4*)(A + (size_t)row*EE + k0 + lc)
                               : make_float4(0,0,0,0);
        As[lc+0][lr] = va.x; As[lc+1][lr] = va.y; As[lc+2][lr] = va.z; As[lc+3][lr] = va.w;
        int rowb = n0 + lr;
        float4 vb = (rowb < SS) ? *(const float4*)(Bm + (size_t)rowb*EE + k0 + lc)
                                : make_float4(0,0,0,0);
        Bs[lc+0][lr] = vb.x; Bs[lc+1][lr] = vb.y; Bs[lc+2][lr] = vb.z; Bs[lc+3][lr] = vb.w;
        __syncthreads();
#pragma unroll
        for (int k = 0; k < 16; k++) {
            float a[4], bb[4];
#pragma unroll
            for (int r = 0; r < 4; r++) a[r]  = As[k][ty*4 + r];
#pragma unroll
            for (int c = 0; c < 4; c++) bb[c] = Bs[k][tx*4 + c];
#pragma unroll
            for (int r = 0; r < 4; r++)
#pragma unroll
                for (int c = 0; c < 4; c++) acc[r][c] += a[r] * bb[c];
        }
        __syncthreads();
    }
#pragma unroll
    for (int r = 0; r < 4; r++) {
        int sRow = m0 + ty*4 + r;
        if (sRow < SS) {
#pragma unroll
            for (int c = 0; c < 4; c++) {
                int tCol = n0 + tx*4 + c;
                if (tCol < SS) Cm[(size_t)sRow*SS + tCol] = acc[r][c];
            }
        }
    }
}

// ---------------- K7: row softmax in-place on g_raw ----------------
__global__ void k_softmax(const float* __restrict__ temp) {
    int bj = blockIdx.x, s = blockIdx.y;
    float* row = g_raw + ((size_t)bj*SS + s)*SS;
    int tid = threadIdx.x;
    int lane = tid & 31, w = tid >> 5;
    __shared__ float sh[7];
    __shared__ float bc;

    float tv = fabsf(temp[0]) * sqrtf((float)SS / 256.0f) + 1e-4f;
    float inv_scale = 1.0f / (16.0f * tv);

    float z = (tid < SS) ? row[tid] * inv_scale : -3.0e38f;
    float m = z;
#pragma unroll
    for (int o = 16; o > 0; o >>= 1) m = fmaxf(m, __shfl_down_sync(0xffffffffu, m, o));
    if (lane == 0) sh[w] = m;
    __syncthreads();
    if (tid == 0) {
        float mm = sh[0];
#pragma unroll
        for (int i = 1; i < 7; i++) mm = fmaxf(mm, sh[i]);
        bc = mm;
    }
    __syncthreads();
    float e = (tid < SS) ? expf(z - bc) : 0.f;
    float sm = e;
#pragma unroll
    for (int o = 16; o > 0; o >>= 1) sm += __shfl_down_sync(0xffffffffu, sm, o);
    if (lane == 0) sh[w] = sm;
    __syncthreads();
    if (tid == 0) {
        float t2 = 0.f;
#pragma unroll
        for (int i = 0; i < 7; i++) t2 += sh[i];
        bc = 1.0f / t2;
    }
    __syncthreads();
    if (tid < SS) row[tid] = e * bc;
}

// ---------------- K8: out = |beta|*W1@xp + |alpha|*xp + |theta|*conv + gamma*comb ----------------
__global__ void k_attn(const float* __restrict__ w3,
                       const float* __restrict__ alpha,
                       const float* __restrict__ beta,
                       const float* __restrict__ theta,
                       const float* __restrict__ gamma,
                       float* __restrict__ outp) {
    int bj = blockIdx.y;
    int j  = bj % JJ;
    int m0 = blockIdx.x * 64;

    const float* A  = g_raw + (size_t)bj*SS*SS;   // softmaxed W1 [S,S]
    const float* Bx = g_xp  + (size_t)bj*SS*OO;   // [S,O]
    const float* Cb = g_comb + (size_t)bj*SS*FF;
    float*       Ob = outp + (size_t)bj*SS*OO;

    __shared__ float As[16][64];
    __shared__ float Bs[16][68];
    __shared__ float w3s[OO*KK];

    int tid = threadIdx.x;
    for (int t = tid; t < OO*KK; t += 256) w3s[t] = w3[(size_t)j*OO*KK + t];

    int lr = tid >> 2;            // 0..63
    int lc = (tid & 3) * 4;       // 0,4,8,12
    int kb = tid >> 4, nb = (tid & 15) * 4;
    int ty = tid >> 4, tx = tid & 15;

    float acc[4][4];
#pragma unroll
    for (int r = 0; r < 4; r++)
#pragma unroll
        for (int c = 0; c < 4; c++) acc[r][c] = 0.f;

    for (int k0 = 0; k0 < SS; k0 += 16) {
        int row = m0 + lr;
#pragma unroll
        for (int kk = 0; kk < 4; kk++) {
            int k = k0 + lc + kk;
            As[lc+kk][lr] = (row < SS && k < SS) ? A[(size_t)row*SS + k] : 0.f;
        }
        int k = k0 + kb;
        float4 vb = (k < SS) ? *(const float4*)(Bx + (size_t)k*OO + nb) : make_float4(0,0,0,0);
        Bs[kb][nb+0] = vb.x; Bs[kb][nb+1] = vb.y; Bs[kb][nb+2] = vb.z; Bs[kb][nb+3] = vb.w;
        __syncthreads();
#pragma unroll
        for (int kk2 = 0; kk2 < 16; kk2++) {
            float a[4], bb[4];
#pragma unroll
            for (int r = 0; r < 4; r++) a[r]  = As[kk2][ty*4 + r];
#pragma unroll
            for (int c = 0; c < 4; c++) bb[c] = Bs[kk2][tx*4 + c];
#pragma unroll
            for (int r = 0; r < 4; r++)
#pragma unroll
                for (int c = 0; c < 4; c++) acc[r][c] += a[r] * bb[c];
        }
        __syncthreads();
    }

    float al = fabsf(alpha[j]), be = fabsf(beta[j]);
    float th = fabsf(theta[j]), ga = gamma[j];

#pragma unroll
    for (int r = 0; r < 4; r++) {
        int s = m0 + ty*4 + r;
        if (s >= SS) continue;
#pragma unroll
        for (int c = 0; c < 4; c++) {
            int o = tx*4 + c;
            float cv = 0.f;
#pragma unroll
            for (int k = 0; k < KK; k++) {
                int si = s + k - 7;
                if (si >= 0 && si < SS) cv += Bx[(size_t)si*OO + o] * w3s[o*KK + k];
            }
            float xpv = Bx[(size_t)s*OO + o];
            Ob[(size_t)s*OO + o] = be*acc[r][c] + al*xpv + th*cv + ga*Cb[(size_t)s*FF + o];
        }
    }
}

// ---------------- launch ----------------
extern "C" void kernel_launch(void* const* d_in, const int* in_sizes, int n_in,
                              void* d_out, int out_size) {
    const float* x_in   = (const float*)d_in[0];
    const float* proj   = (const float*)d_in[1];
    const float* sw     = (const float*)d_in[2];
    const float* tau    = (const float*)d_in[3];
    const float* temp   = (const float*)d_in[4];
    const float* omiga  = (const float*)d_in[5];
    const float* W2     = (const float*)d_in[6];
    const float* bparam = (const float*)d_in[7];
    const float* lnsc   = (const float*)d_in[8];
    const float* lnbi   = (const float*)d_in[9];
    const float* alpha  = (const float*)d_in[10];
    const float* beta   = (const float*)d_in[11];
    const float* theta  = (const float*)d_in[12];
    const float* gamma  = (const float*)d_in[13];
    const float* w3     = (const float*)d_in[14];
    float* outp = (float*)d_out;

    k_reset   <<<2, 256>>>();
    k_maxabs  <<<256, 256>>>(x_in, BB*IN_N*SS*FF);
    k_energy  <<<dim3(BB*IN_N, 8), 256>>>(x_in, sw, omiga);
    k_maskgate<<<2, 256>>>(tau, temp);
    k_combined<<<dim3(BB, 8), 256>>>(x_in, sw, omiga);
    k_xp      <<<dim3(BB*JJ, 4), 256>>>(W2, bparam, lnsc, lnbi);
    k_ktqt    <<<BB*JJ*SS, 256>>>(proj);
    k_gemm    <<<dim3(3, 3, BB*JJ), 256>>>();
    k_softmax <<<dim3(BB*JJ, SS), 224>>>(temp);
    k_attn    <<<dim3(3, BB*JJ), 256>>>(w3, alpha, beta, theta, gamma, outp);

    if (out_size >= 2 * NOUT) {
        void* xp_dev = nullptr;
        cudaGetSymbolAddress(&xp_dev, g_xp);
        cudaMemcpyAsync((float*)d_out + NOUT, xp_dev, (size_t)NOUT * sizeof(float),
                        cudaMemcpyDeviceToDevice);
    }
}

// round 3
// speedup vs baseline: 1.6090x; 1.0707x over previous
#include <cuda_runtime.h>
#include <math.h>

#define BB 8
#define IN_N 8
#define JJ 8
#define SS 187
#define FF 64
#define OO 64
#define CC 67
#define KK 15
#define EE 256
#define SF (SS*FF)
#define NOUT (BB*JJ*SS*OO)
#define ECHUNK 1496   // SF/8

// ---------------- device scratch ----------------
__device__ float g_pmax[148];
__device__ float g_epart[BB*IN_N*8*JJ];   // [bi][chunk][j]
__device__ float g_gate[BB*IN_N*JJ];
__device__ float g_comb[BB*JJ*SS*FF];
__device__ float g_xp  [BB*JJ*SS*OO];
__device__ float g_kt  [BB*JJ*SS*EE];
__device__ float g_qt  [BB*JJ*SS*EE];
__device__ float g_raw [BB*JJ*SS*SS];

// ---------------- f32x2 helpers ----------------
__device__ __forceinline__ unsigned long long pack2(float a) {
    unsigned long long r;
    asm("mov.b64 %0, {%1, %1};" : "=l"(r) : "f"(a));
    return r;
}
__device__ __forceinline__ void ffma2(unsigned long long& d, unsigned long long a,
                                      unsigned long long b) {
    asm("fma.rn.f32x2 %0, %1, %2, %0;" : "+l"(d) : "l"(a), "l"(b));
}
__device__ __forceinline__ void unpack2(unsigned long long v, float& lo, float& hi) {
    asm("mov.b64 {%0, %1}, %2;" : "=f"(lo), "=f"(hi) : "l"(v));
}

// ---------------- K1: per-block max|x| partials ----------------
__global__ void k_maxabs(const float* __restrict__ x, int n) {
    __shared__ float sred[256];
    float m = 0.f;
    for (int i = blockIdx.x * blockDim.x + threadIdx.x; i < n; i += gridDim.x * blockDim.x)
        m = fmaxf(m, fabsf(x[i]));
    sred[threadIdx.x] = m;
    __syncthreads();
    for (int st = 128; st > 0; st >>= 1) {
        if (threadIdx.x < st) sred[threadIdx.x] = fmaxf(sred[threadIdx.x], sred[threadIdx.x + st]);
        __syncthreads();
    }
    if (threadIdx.x == 0) g_pmax[blockIdx.x] = sred[0];
}

__device__ __forceinline__ float reduce_maxv(int tid, float* s_pm) {
    if (tid < 32) {
        float m = 0.f;
        for (int t = tid; t < 148; t += 32) m = fmaxf(m, g_pmax[t]);
#pragma unroll
        for (int o = 16; o > 0; o >>= 1) m = fmaxf(m, __shfl_xor_sync(0xffffffffu, m, o));
        if (tid == 0) *s_pm = m;
    }
    __syncthreads();
    return *s_pm;
}

// ---------------- spline basis ----------------
__device__ __forceinline__ void spline_basis(float x, float inv_maxv_sc, float invh,
                                             float bas[4], int cs[4]) {
    float xn = x * inv_maxv_sc;
    xn = fminf(fmaxf(xn, -0.99f), 0.99f);
    float u = (xn + 1.0f) * invh;
    int c0 = (int)floorf(u) - 1;
#pragma unroll
    for (int k = 0; k < 4; k++) {
        int c = c0 + k;
        float d  = fabsf(u - (float)c);
        float r2 = fmaxf(2.0f - d, 0.f);
        float r1 = fmaxf(1.0f - d, 0.f);
        float v  = r2*r2*r2*(1.0f/6.0f) - r1*r1*r1*(4.0f/6.0f);
        bas[k] = (c >= 0 && c < CC) ? v : 0.f;
        cs[k]  = min(max(c, 0), CC - 1);
    }
}

// ---------------- K2: energy partials (no act store, no atomics) ----------------
__global__ void k_energy(const float* __restrict__ x_in,
                         const float* __restrict__ sw,
                         const float* __restrict__ omiga) {
    int bi = blockIdx.x, i = bi % IN_N, cy = blockIdx.y;
    __shared__ float s_sw[JJ*CC];
    __shared__ float s_om[JJ];
    __shared__ float s_red[8][9];
    __shared__ float s_pm;
    int tid = threadIdx.x;
    float maxv = reduce_maxv(tid, &s_pm) + 1e-8f;
    for (int t = tid; t < JJ*CC; t += blockDim.x) s_sw[t] = sw[i*JJ*CC + t];
    if (tid < JJ) s_om[tid] = fabsf(omiga[i*JJ + tid]);
    __syncthreads();

    float inv_maxv_sc = 0.95f / maxv;
    const float invh = (float)(CC - 1) * 0.5f;
    float acc[JJ];
#pragma unroll
    for (int j = 0; j < JJ; j++) acc[j] = 0.f;

    const float* xb = x_in + (size_t)bi * SF;
    int start = cy * ECHUNK, end = min(SF, start + ECHUNK);
    for (int idx = start + tid; idx < end; idx += blockDim.x) {
        float x = xb[idx];
        float bas[4]; int cs[4];
        spline_basis(x, inv_maxv_sc, invh, bas, cs);
#pragma unroll
        for (int j = 0; j < JJ; j++) {
            const float* swj = s_sw + j*CC;
            float a = bas[0]*swj[cs[0]] + bas[1]*swj[cs[1]]
                    + bas[2]*swj[cs[2]] + bas[3]*swj[cs[3]] + s_om[j] * x;
            acc[j] += a * a;
        }
    }
    int lane = tid & 31, wid = tid >> 5;
#pragma unroll
    for (int j = 0; j < JJ; j++) {
#pragma unroll
        for (int o = 16; o > 0; o >>= 1) acc[j] += __shfl_down_sync(0xffffffffu, acc[j], o);
        if (lane == 0) s_red[wid][j] = acc[j];
    }
    __syncthreads();
    if (tid < JJ) {
        float e = 0.f;
#pragma unroll
        for (int w = 0; w < 8; w++) e += s_red[w][tid];
        g_epart[(bi*8 + cy)*JJ + tid] = e;
    }
}

// ---------------- K3: combined (recompute spline; mask/gate computed in-block) ----------------
__global__ void k_combined(const float* __restrict__ x_in,
                           const float* __restrict__ sw,
                           const float* __restrict__ omiga,
                           const float* __restrict__ tau,
                           const float* __restrict__ temp) {
    int b = blockIdx.x;
    __shared__ float s_sw[IN_N*JJ*CC];
    __shared__ float s_omk[IN_N][JJ];
    __shared__ float s_mask[64];
    __shared__ float s_pm;
    int tid = threadIdx.x;
    float maxv = reduce_maxv(tid, &s_pm) + 1e-8f;

    if (tid < 64) {
        int i = tid >> 3, j = tid & 7;
        int bi = b*IN_N + i;
        float e = 0.f;
#pragma unroll
        for (int c = 0; c < 8; c++) e += g_epart[(bi*8 + c)*JJ + j];
        e *= (1.0f / (float)SF);
        float sq = sqrtf(e + 1e-8f);
        float ta = fabsf(tau[i*JJ + j]);
        float tv = fabsf(temp[0]) * sqrtf((float)SS / 256.0f) + 1e-4f;
        float mk = 1.0f / (1.0f + expf(-(sq - ta) / tv));
        s_mask[tid] = mk;
        if (blockIdx.y == 0) g_gate[bi*JJ + j] = (sq / (ta + 1e-8f)) * mk;
    }
    __syncthreads();
    for (int t = tid; t < IN_N*JJ*CC; t += blockDim.x) {
        int i = t / (JJ*CC), j = (t / CC) % JJ;
        s_sw[t] = sw[t] * s_mask[i*8 + j];
    }
    if (tid < IN_N*JJ) {
        int i = tid >> 3, j = tid & 7;
        s_omk[i][j] = fabsf(omiga[i*JJ + j]) * s_mask[tid];
    }
    __syncthreads();

    float inv_maxv_sc = 0.95f / maxv;
    const float invh = (float)(CC - 1) * 0.5f;
    int start = blockIdx.y * ECHUNK, end = min(SF, start + ECHUNK);
    const float* xb   = x_in + (size_t)b * IN_N * SF;
    float*       cmbb = g_comb + (size_t)b * JJ * SF;

    for (int idx = start + tid; idx < end; idx += blockDim.x) {
        float acc[JJ];
#pragma unroll
        for (int j = 0; j < JJ; j++) acc[j] = 0.f;
#pragma unroll
        for (int i = 0; i < IN_N; i++) {
            float x = xb[(size_t)i*SF + idx];
            float bas[4]; int cs[4];
            spline_basis(x, inv_maxv_sc, invh, bas, cs);
            const float* swi = s_sw + i*JJ*CC;
#pragma unroll
            for (int j = 0; j < JJ; j++) {
                const float* swj = swi + j*CC;
                acc[j] += bas[0]*swj[cs[0]] + bas[1]*swj[cs[1]]
                        + bas[2]*swj[cs[2]] + bas[3]*swj[cs[3]] + s_omk[i][j] * x;
            }
        }
#pragma unroll
        for (int j = 0; j < JJ; j++) cmbb[(size_t)j*SF + idx] = acc[j];
    }
}

// ---------------- K4: combined -> LN -> x_prime ----------------
__global__ void k_xp(const float* __restrict__ W2,
                     const float* __restrict__ bparam,
                     const float* __restrict__ lnsc,
                     const float* __restrict__ lnbi) {
    int bj = blockIdx.x;
    int j  = bj % JJ;
    __shared__ float W2s[FF*OO];
    __shared__ float xlns[4][FF];
    __shared__ float sred[4][2][2];
    __shared__ float s_sc[FF], s_bi[FF];
    for (int t = threadIdx.x; t < FF*OO/4; t += blockDim.x)
        ((float4*)W2s)[t] = ((const float4*)(W2 + (size_t)j*FF*OO))[t];
    if (threadIdx.x < FF) {
        s_sc[threadIdx.x] = lnsc[j*FF + threadIdx.x];
        s_bi[threadIdx.x] = lnbi[j*FF + threadIdx.x];
    }
    __syncthreads();

    int tid = threadIdx.x;
    int r = tid >> 6, f = tid & 63;
    int lane = tid & 31, half = (tid >> 5) & 1;
    int s0 = blockIdx.y * 48;
    const float* cmb = g_comb + (size_t)bj*SS*FF;
    float*       xpb = g_xp   + (size_t)bj*SS*OO;

    for (int it = 0; it < 12; it++) {
        int s = s0 + it*4 + r;
        float c = (s < SS) ? cmb[(size_t)s*FF + f] : 0.f;
        float sm = c, sq = c*c;
#pragma unroll
        for (int o = 16; o > 0; o >>= 1) {
            sm += __shfl_down_sync(0xffffffffu, sm, o);
            sq += __shfl_down_sync(0xffffffffu, sq, o);
        }
        if (lane == 0) { sred[r][half][0] = sm; sred[r][half][1] = sq; }
        __syncthreads();
        float tsum = sred[r][0][0] + sred[r][1][0];
        float tsq  = sred[r][0][1] + sred[r][1][1];
        float mean = tsum * (1.0f/64.0f);
        float var  = tsq * (1.0f/64.0f) - mean*mean;
        float rstd = rsqrtf(var + 1e-5f);
        xlns[r][f] = (c - mean) * rstd * s_sc[f] + s_bi[f];
        __syncthreads();
        if (s < SS) {
            float acc = bparam[((size_t)j*SS + s)*OO + f];
#pragma unroll
            for (int ff = 0; ff < FF; ff++) acc += xlns[r][ff] * W2s[ff*OO + f];
            xpb[(size_t)s*OO + f] = acc;
        }
        __syncthreads();
    }
}

// ---------------- K5: build Kt/Qt + LN(256) ----------------
__global__ void k_ktqt(const float* __restrict__ proj) {
    int id = blockIdx.x;
    int s  = id % SS;
    int bj = id / SS;
    int j  = bj % JJ;
    int b  = bj / JJ;
    int t  = threadIdx.x;
    int m  = t >> 6, d = t & 63;
    int iK = 2*m, iQ = 2*m + 1;

    float kv = proj[(((size_t)(b*IN_N + iK))*SS + s)*FF + d] * g_gate[(b*IN_N + iK)*JJ + j];
    float qv = proj[(((size_t)(b*IN_N + iQ))*SS + s)*FF + d] * g_gate[(b*IN_N + iQ)*JJ + j];

    __shared__ float4 red4[256];
    red4[t] = make_float4(kv, kv*kv, qv, qv*qv);
    __syncthreads();
    for (int st = 128; st > 0; st >>= 1) {
        if (t < st) {
            float4 a = red4[t], c = red4[t + st];
            a.x += c.x; a.y += c.y; a.z += c.z; a.w += c.w;
            red4[t] = a;
        }
        __syncthreads();
    }
    float4 tot = red4[0];
    float km = tot.x * (1.0f/256.0f);
    float kvar = tot.y * (1.0f/256.0f) - km*km;
    float qm = tot.z * (1.0f/256.0f);
    float qvar = tot.w * (1.0f/256.0f) - qm*qm;
    size_t base = ((size_t)bj*SS + s)*EE + t;
    g_kt[base] = (kv - km) * rsqrtf(kvar + 1e-5f);
    g_qt[base] = (qv - qm) * rsqrtf(qvar + 1e-5f);
}

// ---------------- K6: raw = Ktn @ Qtn^T (NT GEMM, f32x2) ----------------
__global__ void k_gemm() {
    int bj = blockIdx.z;
    const float* A  = g_kt + (size_t)bj*SS*EE;
    const float* Bm = g_qt + (size_t)bj*SS*EE;
    float*       Cm = g_raw + (size_t)bj*SS*SS;
    int m0 = blockIdx.y * 64, n0 = blockIdx.x * 64;

    __shared__ float As[16][64];
    __shared__ float Bs[16][64];
    int tid = threadIdx.x;
    int lr  = tid >> 2;
    int lc  = (tid & 3) * 4;
    int ty  = tid >> 4, tx = tid & 15;

    unsigned long long acc[4][2];
#pragma unroll
    for (int r = 0; r < 4; r++) { acc[r][0] = 0ull; acc[r][1] = 0ull; }

    for (int k0 = 0; k0 < EE; k0 += 16) {
        int row = m0 + lr;
        float4 va = (row < SS) ? *(const float4*)(A + (size_t)row*EE + k0 + lc)
                               : make_float4(0,0,0,0);
        As[lc+0][lr] = va.x; As[lc+1][lr] = va.y; As[lc+2][lr] = va.z; As[lc+3][lr] = va.w;
        int rowb = n0 + lr;
        float4 vb = (rowb < SS) ? *(const float4*)(Bm + (size_t)rowb*EE + k0 + lc)
                                : make_float4(0,0,0,0);
        Bs[lc+0][lr] = vb.x; Bs[lc+1][lr] = vb.y; Bs[lc+2][lr] = vb.z; Bs[lc+3][lr] = vb.w;
        __syncthreads();
#pragma unroll
        for (int k = 0; k < 16; k++) {
            float4 a4 = *(const float4*)&As[k][ty*4];
            ulonglong2 b2 = *(const ulonglong2*)&Bs[k][tx*4];
            unsigned long long p0 = pack2(a4.x), p1 = pack2(a4.y);
            unsigned long long p2 = pack2(a4.z), p3 = pack2(a4.w);
            ffma2(acc[0][0], p0, b2.x); ffma2(acc[0][1], p0, b2.y);
            ffma2(acc[1][0], p1, b2.x); ffma2(acc[1][1], p1, b2.y);
            ffma2(acc[2][0], p2, b2.x); ffma2(acc[2][1], p2, b2.y);
            ffma2(acc[3][0], p3, b2.x); ffma2(acc[3][1], p3, b2.y);
        }
        __syncthreads();
    }
#pragma unroll
    for (int r = 0; r < 4; r++) {
        int sRow = m0 + ty*4 + r;
        if (sRow >= SS) continue;
        float c0, c1, c2, c3;
        unpack2(acc[r][0], c0, c1);
        unpack2(acc[r][1], c2, c3);
        int tCol = n0 + tx*4;
        float* dst = Cm + (size_t)sRow*SS + tCol;
        if (tCol + 3 < SS) { dst[0]=c0; dst[1]=c1; dst[2]=c2; dst[3]=c3; }
        else {
            if (tCol+0 < SS) dst[0]=c0;
            if (tCol+1 < SS) dst[1]=c1;
            if (tCol+2 < SS) dst[2]=c2;
            if (tCol+3 < SS) dst[3]=c3;
        }
    }
}

// ---------------- K7: fused softmax + attn GEMM + conv + residual ----------------
// shared: Ast[192][65] (softmaxed W1^T tile), Bxs[192][64] (full xp), w3s[960]
#define AST_LD 65
__global__ void k_attn(const float* __restrict__ w3,
                       const float* __restrict__ alpha,
                       const float* __restrict__ beta,
                       const float* __restrict__ theta,
                       const float* __restrict__ gamma,
                       const float* __restrict__ temp,
                       float* __restrict__ outp) {
    extern __shared__ float smem[];
    float* Ast = smem;                   // 192*65 = 12480
    float* Bxs = Ast + 192*AST_LD;       // 192*64 = 12288
    float* w3s = Bxs + 192*64;           // 960

    int bj = blockIdx.y;
    int j  = bj % JJ;
    int m0 = blockIdx.x * 64;
    int tid = threadIdx.x;

    const float* rawb = g_raw + (size_t)bj*SS*SS;
    const float* Bx   = g_xp  + (size_t)bj*SS*OO;
    const float* Cb   = g_comb + (size_t)bj*SS*FF;
    float*       Ob   = outp + (size_t)bj*SS*OO;

    // load full xp into shared (11968 floats) + zero pad to 12288
    for (int t = tid; t < SS*OO/4; t += 256)
        ((float4*)Bxs)[t] = ((const float4*)Bx)[t];
    for (int t = SS*OO + tid; t < 192*64; t += 256) Bxs[t] = 0.f;
    for (int t = tid; t < OO*KK; t += 256) w3s[t] = w3[(size_t)j*OO*KK + t];

    float tv = fabsf(temp[0]) * sqrtf((float)SS / 256.0f) + 1e-4f;
    float inv_scale = 1.0f / (16.0f * tv);

    // softmax of rows m0..m0+63 into Ast (transposed), zero-padded
    int w = tid >> 5, lane = tid & 31;
    for (int r = w; r < 64; r += 8) {
        int s = m0 + r;
        if (s < SS) {
            float v[6];
            float mx = -3.0e38f;
#pragma unroll
            for (int t = 0; t < 6; t++) {
                int k = lane + 32*t;
                v[t] = (k < SS) ? rawb[(size_t)s*SS + k] * inv_scale : -3.0e38f;
                mx = fmaxf(mx, v[t]);
            }
#pragma unroll
            for (int o = 16; o > 0; o >>= 1) mx = fmaxf(mx, __shfl_xor_sync(0xffffffffu, mx, o));
            float sum = 0.f;
#pragma unroll
            for (int t = 0; t < 6; t++) {
                int k = lane + 32*t;
                v[t] = (k < SS) ? expf(v[t] - mx) : 0.f;
                sum += v[t];
            }
#pragma unroll
            for (int o = 16; o > 0; o >>= 1) sum += __shfl_xor_sync(0xffffffffu, sum, o);
            float inv = 1.0f / sum;
#pragma unroll
            for (int t = 0; t < 6; t++) {
                int k = lane + 32*t;
                Ast[k*AST_LD + r] = v[t] * inv;
            }
        } else {
#pragma unroll
            for (int t = 0; t < 6; t++) Ast[(lane + 32*t)*AST_LD + r] = 0.f;
        }
    }
    __syncthreads();

    // GEMM: out_tile[64 rows][64 cols] = Ast^T @ Bxs over k=0..191
    int ty = tid >> 4, tx = tid & 15;
    unsigned long long acc[4][2];
#pragma unroll
    for (int r = 0; r < 4; r++) { acc[r][0] = 0ull; acc[r][1] = 0ull; }

#pragma unroll 4
    for (int k = 0; k < 192; k++) {
        const float* ap = Ast + k*AST_LD + ty*4;
        float a0 = ap[0], a1 = ap[1], a2 = ap[2], a3 = ap[3];
        ulonglong2 b2 = *(const ulonglong2*)(Bxs + k*64 + tx*4);
        unsigned long long p0 = pack2(a0), p1 = pack2(a1);
        unsigned long long p2 = pack2(a2), p3 = pack2(a3);
        ffma2(acc[0][0], p0, b2.x); ffma2(acc[0][1], p0, b2.y);
        ffma2(acc[1][0], p1, b2.x); ffma2(acc[1][1], p1, b2.y);
        ffma2(acc[2][0], p2, b2.x); ffma2(acc[2][1], p2, b2.y);
        ffma2(acc[3][0], p3, b2.x); ffma2(acc[3][1], p3, b2.y);
    }

    float al = fabsf(alpha[j]), be = fabsf(beta[j]);
    float th = fabsf(theta[j]), ga = gamma[j];

#pragma unroll
    for (int r = 0; r < 4; r++) {
        int s = m0 + ty*4 + r;
        if (s >= SS) continue;
        float cv4[4];
        unpack2(acc[r][0], cv4[0], cv4[1]);
        unpack2(acc[r][1], cv4[2], cv4[3]);
#pragma unroll
        for (int c = 0; c < 4; c++) {
            int o = tx*4 + c;
            float cv = 0.f;
#pragma unroll
            for (int k = 0; k < KK; k++) {
                int si = s + k - 7;
                if (si >= 0 && si < SS) cv += Bxs[si*64 + o] * w3s[o*KK + k];
            }
            float xpv = Bxs[s*64 + o];
            Ob[(size_t)s*OO + o] = be*cv4[c] + al*xpv + th*cv + ga*Cb[(size_t)s*FF + o];
        }
    }
}

// ---------------- launch ----------------
extern "C" void kernel_launch(void* const* d_in, const int* in_sizes, int n_in,
                              void* d_out, int out_size) {
    const float* x_in   = (const float*)d_in[0];
    const float* proj   = (const float*)d_in[1];
    const float* sw     = (const float*)d_in[2];
    const float* tau    = (const float*)d_in[3];
    const float* temp   = (const float*)d_in[4];
    const float* omiga  = (const float*)d_in[5];
    const float* W2     = (const float*)d_in[6];
    const float* bparam = (const float*)d_in[7];
    const float* lnsc   = (const float*)d_in[8];
    const float* lnbi   = (const float*)d_in[9];
    const float* alpha  = (const float*)d_in[10];
    const float* beta   = (const float*)d_in[11];
    const float* theta  = (const float*)d_in[12];
    const float* gamma  = (const float*)d_in[13];
    const float* w3     = (const float*)d_in[14];
    float* outp = (float*)d_out;

    const int attn_smem = (192*AST_LD + 192*64 + OO*KK) * sizeof(float);   // ~103KB
    cudaFuncSetAttribute(k_attn, cudaFuncAttributeMaxDynamicSharedMemorySize, attn_smem);

    k_maxabs  <<<148, 256>>>(x_in, BB*IN_N*SS*FF);
    k_energy  <<<dim3(BB*IN_N, 8), 256>>>(x_in, sw, omiga);
    k_combined<<<dim3(BB, 8), 256>>>(x_in, sw, omiga, tau, temp);
    k_xp      <<<dim3(BB*JJ, 4), 256>>>(W2, bparam, lnsc, lnbi);
    k_ktqt    <<<BB*JJ*SS, 256>>>(proj);
    k_gemm    <<<dim3(3, 3, BB*JJ), 256>>>();
    k_attn    <<<dim3(3, BB*JJ), 256, attn_smem>>>(w3, alpha, beta, theta, gamma, temp, outp);

    if (out_size >= 2 * NOUT) {
        void* xp_dev = nullptr;
        cudaGetSymbolAddress(&xp_dev, g_xp);
        cudaMemcpyAsync((float*)d_out + NOUT, xp_dev, (size_t)NOUT * sizeof(float),
                        cudaMemcpyDeviceToDevice);
    }
}

// round 4
// speedup vs baseline: 2.5165x; 1.5640x over previous
#include <cuda_runtime.h>
#include <math.h>

#define BB 8
#define IN_N 8
#define JJ 8
#define SS 187
#define FF 64
#define OO 64
#define CC 67
#define KK 15
#define SF (SS*FF)
#define NOUT (BB*JJ*SS*OO)
#define ECHUNK 1496    // SF/8  (energy)
#define CCHUNK 748     // SF/16 (combined)

// ---------------- device scratch ----------------
__device__ float g_pmax[148];
__device__ float g_epart[BB*IN_N*8*JJ];
__device__ float g_gate[BB*IN_N*JJ];
__device__ float g_comb[BB*JJ*SS*FF];
__device__ float g_xp  [BB*JJ*SS*OO];
__device__ float g_rs  [BB*IN_N*SS];      // row sums of proj
__device__ float g_ss  [BB*IN_N*SS];      // row sumsq of proj
__device__ float g_P   [BB*4*SS*SS];      // P_m[s,t] per (b,m)

// ---------------- f32x2 helpers ----------------
__device__ __forceinline__ unsigned long long pack2(float a) {
    unsigned long long r;
    asm("mov.b64 %0, {%1, %1};" : "=l"(r) : "f"(a));
    return r;
}
__device__ __forceinline__ void ffma2(unsigned long long& d, unsigned long long a,
                                      unsigned long long b) {
    asm("fma.rn.f32x2 %0, %1, %2, %0;" : "+l"(d) : "l"(a), "l"(b));
}
__device__ __forceinline__ void unpack2(unsigned long long v, float& lo, float& hi) {
    asm("mov.b64 {%0, %1}, %2;" : "=f"(lo), "=f"(hi) : "l"(v));
}

// ---------------- K1: per-block max|x| partials ----------------
__global__ void k_maxabs(const float* __restrict__ x, int n) {
    __shared__ float sred[256];
    float m = 0.f;
    for (int i = blockIdx.x * blockDim.x + threadIdx.x; i < n; i += gridDim.x * blockDim.x)
        m = fmaxf(m, fabsf(x[i]));
    sred[threadIdx.x] = m;
    __syncthreads();
    for (int st = 128; st > 0; st >>= 1) {
        if (threadIdx.x < st) sred[threadIdx.x] = fmaxf(sred[threadIdx.x], sred[threadIdx.x + st]);
        __syncthreads();
    }
    if (threadIdx.x == 0) g_pmax[blockIdx.x] = sred[0];
}

__device__ __forceinline__ float reduce_maxv(int tid, float* s_pm) {
    if (tid < 32) {
        float m = 0.f;
        for (int t = tid; t < 148; t += 32) m = fmaxf(m, g_pmax[t]);
#pragma unroll
        for (int o = 16; o > 0; o >>= 1) m = fmaxf(m, __shfl_xor_sync(0xffffffffu, m, o));
        if (tid == 0) *s_pm = m;
    }
    __syncthreads();
    return *s_pm;
}

// ---------------- spline basis ----------------
__device__ __forceinline__ void spline_basis(float x, float inv_maxv_sc, float invh,
                                             float bas[4], int cs[4]) {
    float xn = x * inv_maxv_sc;
    xn = fminf(fmaxf(xn, -0.99f), 0.99f);
    float u = (xn + 1.0f) * invh;
    int c0 = (int)floorf(u) - 1;
#pragma unroll
    for (int k = 0; k < 4; k++) {
        int c = c0 + k;
        float d  = fabsf(u - (float)c);
        float r2 = fmaxf(2.0f - d, 0.f);
        float r1 = fmaxf(1.0f - d, 0.f);
        float v  = r2*r2*r2*(1.0f/6.0f) - r1*r1*r1*(4.0f/6.0f);
        bas[k] = (c >= 0 && c < CC) ? v : 0.f;
        cs[k]  = min(max(c, 0), CC - 1);
    }
}

// ---------------- K2: energy partials ----------------
__global__ void k_energy(const float* __restrict__ x_in,
                         const float* __restrict__ sw,
                         const float* __restrict__ omiga) {
    int bi = blockIdx.x, i = bi % IN_N, cy = blockIdx.y;
    __shared__ float s_sw[JJ*CC];
    __shared__ float s_om[JJ];
    __shared__ float s_red[8][9];
    __shared__ float s_pm;
    int tid = threadIdx.x;
    float maxv = reduce_maxv(tid, &s_pm) + 1e-8f;
    for (int t = tid; t < JJ*CC; t += blockDim.x) s_sw[t] = sw[i*JJ*CC + t];
    if (tid < JJ) s_om[tid] = fabsf(omiga[i*JJ + tid]);
    __syncthreads();

    float inv_maxv_sc = 0.95f / maxv;
    const float invh = (float)(CC - 1) * 0.5f;
    float acc[JJ];
#pragma unroll
    for (int j = 0; j < JJ; j++) acc[j] = 0.f;

    const float* xb = x_in + (size_t)bi * SF;
    int start = cy * ECHUNK, end = min(SF, start + ECHUNK);
    for (int idx = start + tid; idx < end; idx += blockDim.x) {
        float x = xb[idx];
        float bas[4]; int cs[4];
        spline_basis(x, inv_maxv_sc, invh, bas, cs);
#pragma unroll
        for (int j = 0; j < JJ; j++) {
            const float* swj = s_sw + j*CC;
            float a = bas[0]*swj[cs[0]] + bas[1]*swj[cs[1]]
                    + bas[2]*swj[cs[2]] + bas[3]*swj[cs[3]] + s_om[j] * x;
            acc[j] += a * a;
        }
    }
    int lane = tid & 31, wid = tid >> 5;
#pragma unroll
    for (int j = 0; j < JJ; j++) {
#pragma unroll
        for (int o = 16; o > 0; o >>= 1) acc[j] += __shfl_down_sync(0xffffffffu, acc[j], o);
        if (lane == 0) s_red[wid][j] = acc[j];
    }
    __syncthreads();
    if (tid < JJ) {
        float e = 0.f;
#pragma unroll
        for (int w = 0; w < 8; w++) e += s_red[w][tid];
        g_epart[(bi*8 + cy)*JJ + tid] = e;
    }
}

// ---------------- K3: combined ----------------
__global__ void k_combined(const float* __restrict__ x_in,
                           const float* __restrict__ sw,
                           const float* __restrict__ omiga,
                           const float* __restrict__ tau,
                           const float* __restrict__ temp) {
    int b = blockIdx.x;
    __shared__ float s_sw[IN_N*JJ*CC];
    __shared__ float s_omk[IN_N][JJ];
    __shared__ float s_mask[64];
    __shared__ float s_pm;
    int tid = threadIdx.x;
    float maxv = reduce_maxv(tid, &s_pm) + 1e-8f;

    if (tid < 64) {
        int i = tid >> 3, j = tid & 7;
        int bi = b*IN_N + i;
        float e = 0.f;
#pragma unroll
        for (int c = 0; c < 8; c++) e += g_epart[(bi*8 + c)*JJ + j];
        e *= (1.0f / (float)SF);
        float sq = sqrtf(e + 1e-8f);
        float ta = fabsf(tau[i*JJ + j]);
        float tv = fabsf(temp[0]) * sqrtf((float)SS / 256.0f) + 1e-4f;
        float mk = 1.0f / (1.0f + expf(-(sq - ta) / tv));
        s_mask[tid] = mk;
        if (blockIdx.y == 0) g_gate[bi*JJ + j] = (sq / (ta + 1e-8f)) * mk;
    }
    __syncthreads();
    for (int t = tid; t < IN_N*JJ*CC; t += blockDim.x) {
        int i = t / (JJ*CC), j = (t / CC) % JJ;
        s_sw[t] = sw[t] * s_mask[i*8 + j];
    }
    if (tid < IN_N*JJ) {
        int i = tid >> 3, j = tid & 7;
        s_omk[i][j] = fabsf(omiga[i*JJ + j]) * s_mask[tid];
    }
    __syncthreads();

    float inv_maxv_sc = 0.95f / maxv;
    const float invh = (float)(CC - 1) * 0.5f;
    int start = blockIdx.y * CCHUNK, end = min(SF, start + CCHUNK);
    const float* xb   = x_in + (size_t)b * IN_N * SF;
    float*       cmbb = g_comb + (size_t)b * JJ * SF;

    for (int idx = start + tid; idx < end; idx += blockDim.x) {
        float acc[JJ];
#pragma unroll
        for (int j = 0; j < JJ; j++) acc[j] = 0.f;
#pragma unroll
        for (int i = 0; i < IN_N; i++) {
            float x = xb[(size_t)i*SF + idx];
            float bas[4]; int cs[4];
            spline_basis(x, inv_maxv_sc, invh, bas, cs);
            const float* swi = s_sw + i*JJ*CC;
#pragma unroll
            for (int j = 0; j < JJ; j++) {
                const float* swj = swi + j*CC;
                acc[j] += bas[0]*swj[cs[0]] + bas[1]*swj[cs[1]]
                        + bas[2]*swj[cs[2]] + bas[3]*swj[cs[3]] + s_omk[i][j] * x;
            }
        }
#pragma unroll
        for (int j = 0; j < JJ; j++) cmbb[(size_t)j*SF + idx] = acc[j];
    }
}

// ---------------- K4: combined -> LN -> x_prime (warp-per-row, no block barriers) ----------------
__global__ void k_xp(const float* __restrict__ W2,
                     const float* __restrict__ bparam,
                     const float* __restrict__ lnsc,
                     const float* __restrict__ lnbi) {
    int bj = blockIdx.x;
    int j  = bj % JJ;
    __shared__ float W2s[FF*OO];
    __shared__ float s_sc[FF], s_bi[FF];
    __shared__ float xlnw[8][FF];
    int tid = threadIdx.x;
    for (int t = tid; t < FF*OO/4; t += blockDim.x)
        ((float4*)W2s)[t] = ((const float4*)(W2 + (size_t)j*FF*OO))[t];
    if (tid < FF) {
        s_sc[tid] = lnsc[j*FF + tid];
        s_bi[tid] = lnbi[j*FF + tid];
    }
    __syncthreads();

    int w = tid >> 5, lane = tid & 31;
    int s0 = blockIdx.y * 48;
    const float* cmb = g_comb + (size_t)bj*SS*FF;
    float*       xpb = g_xp   + (size_t)bj*SS*OO;
    const float* bpj = bparam + (size_t)j*SS*OO;

#pragma unroll
    for (int it = 0; it < 6; it++) {
        int s = s0 + it*8 + w;
        if (s >= SS) break;
        float c0 = cmb[(size_t)s*FF + lane];
        float c1 = cmb[(size_t)s*FF + lane + 32];
        float sm = c0 + c1, sq = c0*c0 + c1*c1;
#pragma unroll
        for (int o = 16; o > 0; o >>= 1) {
            sm += __shfl_xor_sync(0xffffffffu, sm, o);
            sq += __shfl_xor_sync(0xffffffffu, sq, o);
        }
        float mean = sm * (1.0f/64.0f);
        float var  = sq * (1.0f/64.0f) - mean*mean;
        float rstd = rsqrtf(var + 1e-5f);
        xlnw[w][lane]      = (c0 - mean)*rstd*s_sc[lane]      + s_bi[lane];
        xlnw[w][lane + 32] = (c1 - mean)*rstd*s_sc[lane + 32] + s_bi[lane + 32];
        __syncwarp();
        unsigned long long acc = *(const unsigned long long*)(bpj + (size_t)s*OO + 2*lane);
#pragma unroll
        for (int ff = 0; ff < FF; ff++)
            ffma2(acc, pack2(xlnw[w][ff]), *(const unsigned long long*)&W2s[ff*OO + 2*lane]);
        *(unsigned long long*)(xpb + (size_t)s*OO + 2*lane) = acc;
        __syncwarp();
    }
}

// ---------------- K5: per-row sums/sumsqs of proj ----------------
__global__ void k_stats(const float* __restrict__ proj) {
    int bi = blockIdx.x;
    int w = threadIdx.x >> 5, lane = threadIdx.x & 31;
    const float* pb = proj + (size_t)bi*SS*FF;
    for (int s = w; s < SS; s += 8) {
        float a = pb[(size_t)s*FF + lane];
        float c = pb[(size_t)s*FF + lane + 32];
        float sm = a + c, sq = a*a + c*c;
#pragma unroll
        for (int o = 16; o > 0; o >>= 1) {
            sm += __shfl_xor_sync(0xffffffffu, sm, o);
            sq += __shfl_xor_sync(0xffffffffu, sq, o);
        }
        if (lane == 0) { g_rs[bi*SS + s] = sm; g_ss[bi*SS + s] = sq; }
    }
}

// ---------------- K6: P_m = projK @ projQ^T (NT GEMM, k=64, f32x2) ----------------
__global__ void k_pgemm(const float* __restrict__ proj) {
    int bm = blockIdx.z;             // b*4 + m
    int b = bm >> 2, m = bm & 3;
    const float* A  = proj + ((size_t)(b*IN_N + 2*m    )*SS)*FF;
    const float* Bm = proj + ((size_t)(b*IN_N + 2*m + 1)*SS)*FF;
    float*       Cm = g_P + (size_t)bm*SS*SS;
    int m0 = blockIdx.y * 64, n0 = blockIdx.x * 64;

    __shared__ float As[16][64];
    __shared__ float Bs[16][64];
    int tid = threadIdx.x;
    int lr  = tid >> 2;
    int lc  = (tid & 3) * 4;
    int ty  = tid >> 4, tx = tid & 15;

    unsigned long long acc[4][2];
#pragma unroll
    for (int r = 0; r < 4; r++) { acc[r][0] = 0ull; acc[r][1] = 0ull; }

    for (int k0 = 0; k0 < FF; k0 += 16) {
        int row = m0 + lr;
        float4 va = (row < SS) ? *(const float4*)(A + (size_t)row*FF + k0 + lc)
                               : make_float4(0,0,0,0);
        As[lc+0][lr] = va.x; As[lc+1][lr] = va.y; As[lc+2][lr] = va.z; As[lc+3][lr] = va.w;
        int rowb = n0 + lr;
        float4 vb = (rowb < SS) ? *(const float4*)(Bm + (size_t)rowb*FF + k0 + lc)
                                : make_float4(0,0,0,0);
        Bs[lc+0][lr] = vb.x; Bs[lc+1][lr] = vb.y; Bs[lc+2][lr] = vb.z; Bs[lc+3][lr] = vb.w;
        __syncthreads();
#pragma unroll
        for (int k = 0; k < 16; k++) {
            float4 a4 = *(const float4*)&As[k][ty*4];
            ulonglong2 b2 = *(const ulonglong2*)&Bs[k][tx*4];
            unsigned long long p0 = pack2(a4.x), p1 = pack2(a4.y);
            unsigned long long p2 = pack2(a4.z), p3 = pack2(a4.w);
            ffma2(acc[0][0], p0, b2.x); ffma2(acc[0][1], p0, b2.y);
            ffma2(acc[1][0], p1, b2.x); ffma2(acc[1][1], p1, b2.y);
            ffma2(acc[2][0], p2, b2.x); ffma2(acc[2][1], p2, b2.y);
            ffma2(acc[3][0], p3, b2.x); ffma2(acc[3][1], p3, b2.y);
        }
        __syncthreads();
    }
#pragma unroll
    for (int r = 0; r < 4; r++) {
        int sRow = m0 + ty*4 + r;
        if (sRow >= SS) continue;
        float c0, c1, c2, c3;
        unpack2(acc[r][0], c0, c1);
        unpack2(acc[r][1], c2, c3);
        int tCol = n0 + tx*4;
        float* dst = Cm + (size_t)sRow*SS + tCol;
        if (tCol + 3 < SS) { dst[0]=c0; dst[1]=c1; dst[2]=c2; dst[3]=c3; }
        else {
            if (tCol+0 < SS) dst[0]=c0;
            if (tCol+1 < SS) dst[1]=c1;
            if (tCol+2 < SS) dst[2]=c2;
            if (tCol+3 < SS) dst[3]=c3;
        }
    }
}

// ---------------- K7: fused raw-reconstruct + softmax + attn GEMM + conv + residual ----
#define AST_LD 65
__global__ void k_attn(const float* __restrict__ w3,
                       const float* __restrict__ alpha,
                       const float* __restrict__ beta,
                       const float* __restrict__ theta,
                       const float* __restrict__ gamma,
                       const float* __restrict__ temp,
                       float* __restrict__ outp) {
    extern __shared__ float smem[];
    float* Ast = smem;                   // 192*65
    float* Bxs = Ast + 192*AST_LD;       // 192*64
    float* w3s = Bxs + 192*64;           // 960
    __shared__ float qr_sh[SS], qmr_sh[SS];
    __shared__ float km_sh[64], As_sh[64];
    __shared__ float a_sh[4];

    int bj = blockIdx.y;
    int j  = bj & 7, b = bj >> 3;
    int m0 = blockIdx.x * 64;
    int tid = threadIdx.x;

    const float* Bx = g_xp  + (size_t)bj*SS*OO;
    const float* Cb = g_comb + (size_t)bj*SS*FF;
    float*       Ob = outp + (size_t)bj*SS*OO;

    float tv = fabsf(temp[0]) * sqrtf((float)SS / 256.0f) + 1e-4f;
    float inv_scale = 1.0f / (16.0f * tv);

    for (int t = tid; t < SS*OO/4; t += 256)
        ((float4*)Bxs)[t] = ((const float4*)Bx)[t];
    for (int t = SS*OO + tid; t < 192*64; t += 256) Bxs[t] = 0.f;
    for (int t = tid; t < OO*KK; t += 256) w3s[t] = w3[(size_t)j*OO*KK + t];

    if (tid < 4) {
        float gK = g_gate[(b*IN_N + 2*tid    )*JJ + j];
        float gQ = g_gate[(b*IN_N + 2*tid + 1)*JJ + j];
        a_sh[tid] = gK * gQ;
    }
    // column (Q-side) stats for all t
    if (tid < SS) {
        float qm = 0.f, qs = 0.f;
#pragma unroll
        for (int m = 0; m < 4; m++) {
            int bi = b*IN_N + 2*m + 1;
            float g = g_gate[bi*JJ + j];
            qm += g * g_rs[bi*SS + tid];
            qs += g * g * g_ss[bi*SS + tid];
        }
        qm *= (1.0f/256.0f); qs *= (1.0f/256.0f);
        float qr = rsqrtf(qs - qm*qm + 1e-5f);
        qr_sh[tid]  = qr;
        qmr_sh[tid] = 256.0f * qm * qr;
    }
    // row (K-side) stats for this tile
    if (tid >= 192) {
        int r = tid - 192;
        int s = m0 + r;
        if (s < SS) {
            float km = 0.f, ks = 0.f;
#pragma unroll
            for (int m = 0; m < 4; m++) {
                int bi = b*IN_N + 2*m;
                float g = g_gate[bi*JJ + j];
                km += g * g_rs[bi*SS + s];
                ks += g * g * g_ss[bi*SS + s];
            }
            km *= (1.0f/256.0f); ks *= (1.0f/256.0f);
            float kr = rsqrtf(ks - km*km + 1e-5f);
            km_sh[r] = km;
            As_sh[r] = inv_scale * kr;
        }
    }
    __syncthreads();

    float a0 = a_sh[0], a1 = a_sh[1], a2 = a_sh[2], a3 = a_sh[3];
    const float* Pb = g_P + (size_t)(b*4)*SS*SS;

    int w = tid >> 5, lane = tid & 31;
    for (int r = w; r < 64; r += 8) {
        int s = m0 + r;
        if (s < SS) {
            float km = km_sh[r], Asc = As_sh[r];
            const float* P0 = Pb + (size_t)0*SS*SS + (size_t)s*SS;
            const float* P1 = Pb + (size_t)1*SS*SS + (size_t)s*SS;
            const float* P2 = Pb + (size_t)2*SS*SS + (size_t)s*SS;
            const float* P3 = Pb + (size_t)3*SS*SS + (size_t)s*SS;
            float v[6];
            float mx = -3.0e38f;
#pragma unroll
            for (int u = 0; u < 6; u++) {
                int t = lane + 32*u;
                if (t < SS) {
                    float G = a0*P0[t] + a1*P1[t] + a2*P2[t] + a3*P3[t];
                    v[u] = Asc * (qr_sh[t]*G - km*qmr_sh[t]);
                } else v[u] = -3.0e38f;
                mx = fmaxf(mx, v[u]);
            }
#pragma unroll
            for (int o = 16; o > 0; o >>= 1) mx = fmaxf(mx, __shfl_xor_sync(0xffffffffu, mx, o));
            float sum = 0.f;
#pragma unroll
            for (int u = 0; u < 6; u++) {
                int t = lane + 32*u;
                v[u] = (t < SS) ? expf(v[u] - mx) : 0.f;
                sum += v[u];
            }
#pragma unroll
            for (int o = 16; o > 0; o >>= 1) sum += __shfl_xor_sync(0xffffffffu, sum, o);
            float inv = 1.0f / sum;
#pragma unroll
            for (int u = 0; u < 6; u++) Ast[(lane + 32*u)*AST_LD + r] = v[u] * inv;
        } else {
#pragma unroll
            for (int u = 0; u < 6; u++) Ast[(lane + 32*u)*AST_LD + r] = 0.f;
        }
    }
    __syncthreads();

    int ty = tid >> 4, tx = tid & 15;
    unsigned long long acc[4][2];
#pragma unroll
    for (int r = 0; r < 4; r++) { acc[r][0] = 0ull; acc[r][1] = 0ull; }

#pragma unroll 4
    for (int k = 0; k < 192; k++) {
        const float* ap = Ast + k*AST_LD + ty*4;
        float b0 = ap[0], b1 = ap[1], b2v = ap[2], b3 = ap[3];
        ulonglong2 bp = *(const ulonglong2*)(Bxs + k*64 + tx*4);
        unsigned long long p0 = pack2(b0), p1 = pack2(b1);
        unsigned long long p2 = pack2(b2v), p3 = pack2(b3);
        ffma2(acc[0][0], p0, bp.x); ffma2(acc[0][1], p0, bp.y);
        ffma2(acc[1][0], p1, bp.x); ffma2(acc[1][1], p1, bp.y);
        ffma2(acc[2][0], p2, bp.x); ffma2(acc[2][1], p2, bp.y);
        ffma2(acc[3][0], p3, bp.x); ffma2(acc[3][1], p3, bp.y);
    }

    float al = fabsf(alpha[j]), be = fabsf(beta[j]);
    float th = fabsf(theta[j]), ga = gamma[j];

#pragma unroll
    for (int r = 0; r < 4; r++) {
        int s = m0 + ty*4 + r;
        if (s >= SS) continue;
        float cv4[4];
        unpack2(acc[r][0], cv4[0], cv4[1]);
        unpack2(acc[r][1], cv4[2], cv4[3]);
#pragma unroll
        for (int c = 0; c < 4; c++) {
            int o = tx*4 + c;
            float cv = 0.f;
#pragma unroll
            for (int k = 0; k < KK; k++) {
                int si = s + k - 7;
                if (si >= 0 && si < SS) cv += Bxs[si*64 + o] * w3s[o*KK + k];
            }
            float xpv = Bxs[s*64 + o];
            Ob[(size_t)s*OO + o] = be*cv4[c] + al*xpv + th*cv + ga*Cb[(size_t)s*FF + o];
        }
    }
}

// ---------------- launch ----------------
extern "C" void kernel_launch(void* const* d_in, const int* in_sizes, int n_in,
                              void* d_out, int out_size) {
    const float* x_in   = (const float*)d_in[0];
    const float* proj   = (const float*)d_in[1];
    const float* sw     = (const float*)d_in[2];
    const float* tau    = (const float*)d_in[3];
    const float* temp   = (const float*)d_in[4];
    const float* omiga  = (const float*)d_in[5];
    const float* W2     = (const float*)d_in[6];
    const float* bparam = (const float*)d_in[7];
    const float* lnsc   = (const float*)d_in[8];
    const float* lnbi   = (const float*)d_in[9];
    const float* alpha  = (const float*)d_in[10];
    const float* beta   = (const float*)d_in[11];
    const float* theta  = (const float*)d_in[12];
    const float* gamma  = (const float*)d_in[13];
    const float* w3     = (const float*)d_in[14];
    float* outp = (float*)d_out;

    const int attn_smem = (192*AST_LD + 192*64 + OO*KK) * sizeof(float);
    cudaFuncSetAttribute(k_attn, cudaFuncAttributeMaxDynamicSharedMemorySize, attn_smem);

    k_maxabs  <<<148, 256>>>(x_in, BB*IN_N*SS*FF);
    k_stats   <<<BB*IN_N, 256>>>(proj);
    k_pgemm   <<<dim3(3, 3, BB*4), 256>>>(proj);
    k_energy  <<<dim3(BB*IN_N, 8), 256>>>(x_in, sw, omiga);
    k_combined<<<dim3(BB, 16), 256>>>(x_in, sw, omiga, tau, temp);
    k_xp      <<<dim3(BB*JJ, 4), 256>>>(W2, bparam, lnsc, lnbi);
    k_attn    <<<dim3(3, BB*JJ), 256, attn_smem>>>(w3, alpha, beta, theta, gamma, temp, outp);

    if (out_size >= 2 * NOUT) {
        void* xp_dev = nullptr;
        cudaGetSymbolAddress(&xp_dev, g_xp);
        cudaMemcpyAsync((float*)d_out + NOUT, xp_dev, (size_t)NOUT * sizeof(float),
                        cudaMemcpyDeviceToDevice);
    }
}

// round 5
// speedup vs baseline: 2.8175x; 1.1196x over previous
#include <cuda_runtime.h>
#include <math.h>

#define BB 8
#define IN_N 8
#define JJ 8
#define SS 187
#define FF 64
#define OO 64
#define CC 67
#define KK 15
#define SF (SS*FF)
#define NOUT (BB*JJ*SS*OO)
#define ECHUNK 1496    // SF/8

// ---------------- device scratch ----------------
__device__ float g_pmax[148];
__device__ float g_epart[BB*IN_N*8*JJ];
__device__ float g_gate[BB*IN_N*JJ];
__device__ float g_act [BB*IN_N*JJ*SF];   // 24.5 MB
__device__ float g_comb[BB*JJ*SS*FF];
__device__ float g_xp  [BB*JJ*SS*OO];
__device__ float g_rs  [BB*IN_N*SS];
__device__ float g_ss  [BB*IN_N*SS];
__device__ float g_P   [BB*4*SS*SS];

// ---------------- f32x2 helpers ----------------
__device__ __forceinline__ unsigned long long pack2(float a) {
    unsigned long long r;
    asm("mov.b64 %0, {%1, %1};" : "=l"(r) : "f"(a));
    return r;
}
__device__ __forceinline__ void ffma2(unsigned long long& d, unsigned long long a,
                                      unsigned long long b) {
    asm("fma.rn.f32x2 %0, %1, %2, %0;" : "+l"(d) : "l"(a), "l"(b));
}
__device__ __forceinline__ void unpack2(unsigned long long v, float& lo, float& hi) {
    asm("mov.b64 {%0, %1}, %2;" : "=f"(lo), "=f"(hi) : "l"(v));
}

// ---------------- K1: fused maxabs partials + proj row stats ----------------
__global__ void k_prep(const float* __restrict__ x, int n, const float* __restrict__ proj) {
    if (blockIdx.x < 148) {
        __shared__ float sred[256];
        float m = 0.f;
        for (int i = blockIdx.x * blockDim.x + threadIdx.x; i < 148 * blockDim.x * ((n + 148*256 - 1)/(148*256)); )
            break;  // (placeholder not used)
        // grid-stride over x with 148 blocks
        for (int i = blockIdx.x * 256 + threadIdx.x; i < n; i += 148 * 256)
            m = fmaxf(m, fabsf(x[i]));
        sred[threadIdx.x] = m;
        __syncthreads();
        for (int st = 128; st > 0; st >>= 1) {
            if (threadIdx.x < st) sred[threadIdx.x] = fmaxf(sred[threadIdx.x], sred[threadIdx.x + st]);
            __syncthreads();
        }
        if (threadIdx.x == 0) g_pmax[blockIdx.x] = sred[0];
    } else {
        int bi = blockIdx.x - 148;
        int w = threadIdx.x >> 5, lane = threadIdx.x & 31;
        const float* pb = proj + (size_t)bi*SS*FF;
        for (int s = w; s < SS; s += 8) {
            float a = pb[(size_t)s*FF + lane];
            float c = pb[(size_t)s*FF + lane + 32];
            float sm = a + c, sq = a*a + c*c;
#pragma unroll
            for (int o = 16; o > 0; o >>= 1) {
                sm += __shfl_xor_sync(0xffffffffu, sm, o);
                sq += __shfl_xor_sync(0xffffffffu, sq, o);
            }
            if (lane == 0) { g_rs[bi*SS + s] = sm; g_ss[bi*SS + s] = sq; }
        }
    }
}

__device__ __forceinline__ float reduce_maxv(int tid, float* s_pm) {
    if (tid < 32) {
        float m = 0.f;
        for (int t = tid; t < 148; t += 32) m = fmaxf(m, g_pmax[t]);
#pragma unroll
        for (int o = 16; o > 0; o >>= 1) m = fmaxf(m, __shfl_xor_sync(0xffffffffu, m, o));
        if (tid == 0) *s_pm = m;
    }
    __syncthreads();
    return *s_pm;
}

// closed-form cubic B-spline taps; zero out-of-range edge taps
__device__ __forceinline__ void spline_basis(float x, float inv_maxv_sc, float invh,
                                             float bas[4], int& c0) {
    float xn = x * inv_maxv_sc;
    xn = fminf(fmaxf(xn, -0.99f), 0.99f);
    float u = (xn + 1.0f) * invh;
    float fl = floorf(u);
    float t = u - fl;
    int fli = (int)fl;
    c0 = fli - 1;
    float omt = 1.0f - t;
    float t2 = t*t, t3 = t2*t;
    float o2 = omt*omt, o3 = o2*omt;
    float b0 = o3 * (1.0f/6.0f);
    float b1 = (2.0f-t)*(2.0f-t)*(2.0f-t)*(1.0f/6.0f) - o3*(4.0f/6.0f);
    float b2 = (1.0f+t)*(1.0f+t)*(1.0f+t)*(1.0f/6.0f) - t3*(4.0f/6.0f);
    float b3 = t3 * (1.0f/6.0f);
    bas[0] = (fli >= 1)  ? b0 : 0.f;
    bas[1] = b1;
    bas[2] = b2;
    bas[3] = (fli <= 64) ? b3 : 0.f;
}

// ---------------- K2: spline -> activated store + energy partials (single pass) ----------------
__global__ void k_spline(const float* __restrict__ x_in,
                         const float* __restrict__ sw,
                         const float* __restrict__ omiga) {
    int bi = blockIdx.x, i = bi % IN_N, cy = blockIdx.y;
    __shared__ float s_sw[JJ*CC];
    __shared__ float s_om[JJ];
    __shared__ float s_red[8][9];
    __shared__ float s_pm;
    int tid = threadIdx.x;
    float maxv = reduce_maxv(tid, &s_pm) + 1e-8f;
    for (int t = tid; t < JJ*CC; t += blockDim.x) s_sw[t] = sw[i*JJ*CC + t];
    if (tid < JJ) s_om[tid] = fabsf(omiga[i*JJ + tid]);
    __syncthreads();

    float inv_maxv_sc = 0.95f / maxv;
    const float invh = (float)(CC - 1) * 0.5f;
    float acc[JJ];
#pragma unroll
    for (int j = 0; j < JJ; j++) acc[j] = 0.f;

    const float* xb   = x_in + (size_t)bi * SF;
    float*       actb = g_act + (size_t)bi * JJ * SF;
    int start = cy * ECHUNK, end = min(SF, start + ECHUNK);
    for (int idx = start + tid; idx < end; idx += blockDim.x) {
        float x = xb[idx];
        float bas[4]; int c0;
        spline_basis(x, inv_maxv_sc, invh, bas, c0);
        int i0 = max(c0, 0);        // safe base (only edge taps are zeroed)
#pragma unroll
        for (int j = 0; j < JJ; j++) {
            const float* swj = s_sw + j*CC;
            // taps at c0..c0+3; bas[0]=0 when c0<0, bas[3]=0 when c0+3>66
            float a = bas[0]*swj[i0] + bas[1]*swj[c0+1] + bas[2]*swj[c0+2]
                    + bas[3]*swj[min(c0+3, CC-1)] + s_om[j] * x;
            actb[(size_t)j*SF + idx] = a;
            acc[j] += a * a;
        }
    }
    int lane = tid & 31, wid = tid >> 5;
#pragma unroll
    for (int j = 0; j < JJ; j++) {
#pragma unroll
        for (int o = 16; o > 0; o >>= 1) acc[j] += __shfl_down_sync(0xffffffffu, acc[j], o);
        if (lane == 0) s_red[wid][j] = acc[j];
    }
    __syncthreads();
    if (tid < JJ) {
        float e = 0.f;
#pragma unroll
        for (int w = 0; w < 8; w++) e += s_red[w][tid];
        g_epart[(bi*8 + cy)*JJ + tid] = e;
    }
}

// ---------------- K3: combined = masked i-sum over activated (bandwidth-only) ----------------
__global__ void k_combined(const float* __restrict__ tau, const float* __restrict__ temp) {
    int bj = blockIdx.x;
    int b = bj >> 3, j = bj & 7;
    __shared__ float s_mask[IN_N];
    int tid = threadIdx.x;
    if (tid < IN_N) {
        int i = tid;
        int bi = b*IN_N + i;
        float e = 0.f;
#pragma unroll
        for (int c = 0; c < 8; c++) e += g_epart[(bi*8 + c)*JJ + j];
        e *= (1.0f / (float)SF);
        float sq = sqrtf(e + 1e-8f);
        float ta = fabsf(tau[i*JJ + j]);
        float tv = fabsf(temp[0]) * sqrtf((float)SS / 256.0f) + 1e-4f;
        float mk = 1.0f / (1.0f + expf(-(sq - ta) / tv));
        s_mask[tid] = mk;
        if (blockIdx.y == 0) g_gate[bi*JJ + j] = (sq / (ta + 1e-8f)) * mk;
    }
    __syncthreads();
    float m0 = s_mask[0], m1 = s_mask[1], m2 = s_mask[2], m3 = s_mask[3];
    float m4 = s_mask[4], m5 = s_mask[5], m6 = s_mask[6], m7 = s_mask[7];

    // float4 over SF: 2992 float4s, 8 chunks of 374
    const float4* a0 = (const float4*)(g_act + ((size_t)(b*IN_N + 0)*JJ + j)*SF);
    const float4* a1 = (const float4*)(g_act + ((size_t)(b*IN_N + 1)*JJ + j)*SF);
    const float4* a2 = (const float4*)(g_act + ((size_t)(b*IN_N + 2)*JJ + j)*SF);
    const float4* a3 = (const float4*)(g_act + ((size_t)(b*IN_N + 3)*JJ + j)*SF);
    const float4* a4 = (const float4*)(g_act + ((size_t)(b*IN_N + 4)*JJ + j)*SF);
    const float4* a5 = (const float4*)(g_act + ((size_t)(b*IN_N + 5)*JJ + j)*SF);
    const float4* a6 = (const float4*)(g_act + ((size_t)(b*IN_N + 6)*JJ + j)*SF);
    const float4* a7 = (const float4*)(g_act + ((size_t)(b*IN_N + 7)*JJ + j)*SF);
    float4* cm = (float4*)(g_comb + (size_t)bj*SF);

    int n4 = SF/4;                     // 2992
    int start = blockIdx.y * 374, end = min(n4, start + 374);
    for (int v = start + tid; v < end; v += blockDim.x) {
        float4 r0 = a0[v], r1 = a1[v], r2 = a2[v], r3 = a3[v];
        float4 r4 = a4[v], r5 = a5[v], r6 = a6[v], r7 = a7[v];
        float4 o;
        o.x = m0*r0.x + m1*r1.x + m2*r2.x + m3*r3.x + m4*r4.x + m5*r5.x + m6*r6.x + m7*r7.x;
        o.y = m0*r0.y + m1*r1.y + m2*r2.y + m3*r3.y + m4*r4.y + m5*r5.y + m6*r6.y + m7*r7.y;
        o.z = m0*r0.z + m1*r1.z + m2*r2.z + m3*r3.z + m4*r4.z + m5*r5.z + m6*r6.z + m7*r7.z;
        o.w = m0*r0.w + m1*r1.w + m2*r2.w + m3*r3.w + m4*r4.w + m5*r5.w + m6*r6.w + m7*r7.w;
        cm[v] = o;
    }
}

// ---------------- K4: combined -> LN -> x_prime (warp-per-row) ----------------
__global__ void k_xp(const float* __restrict__ W2,
                     const float* __restrict__ bparam,
                     const float* __restrict__ lnsc,
                     const float* __restrict__ lnbi) {
    int bj = blockIdx.x;
    int j  = bj % JJ;
    __shared__ float W2s[FF*OO];
    __shared__ float s_sc[FF], s_bi[FF];
    __shared__ float xlnw[8][FF];
    int tid = threadIdx.x;
    for (int t = tid; t < FF*OO/4; t += blockDim.x)
        ((float4*)W2s)[t] = ((const float4*)(W2 + (size_t)j*FF*OO))[t];
    if (tid < FF) {
        s_sc[tid] = lnsc[j*FF + tid];
        s_bi[tid] = lnbi[j*FF + tid];
    }
    __syncthreads();

    int w = tid >> 5, lane = tid & 31;
    int s0 = blockIdx.y * 48;
    const float* cmb = g_comb + (size_t)bj*SS*FF;
    float*       xpb = g_xp   + (size_t)bj*SS*OO;
    const float* bpj = bparam + (size_t)j*SS*OO;

#pragma unroll
    for (int it = 0; it < 6; it++) {
        int s = s0 + it*8 + w;
        if (s >= SS) break;
        float c0 = cmb[(size_t)s*FF + lane];
        float c1 = cmb[(size_t)s*FF + lane + 32];
        float sm = c0 + c1, sq = c0*c0 + c1*c1;
#pragma unroll
        for (int o = 16; o > 0; o >>= 1) {
            sm += __shfl_xor_sync(0xffffffffu, sm, o);
            sq += __shfl_xor_sync(0xffffffffu, sq, o);
        }
        float mean = sm * (1.0f/64.0f);
        float var  = sq * (1.0f/64.0f) - mean*mean;
        float rstd = rsqrtf(var + 1e-5f);
        xlnw[w][lane]      = (c0 - mean)*rstd*s_sc[lane]      + s_bi[lane];
        xlnw[w][lane + 32] = (c1 - mean)*rstd*s_sc[lane + 32] + s_bi[lane + 32];
        __syncwarp();
        unsigned long long acc = *(const unsigned long long*)(bpj + (size_t)s*OO + 2*lane);
#pragma unroll
        for (int ff = 0; ff < FF; ff++)
            ffma2(acc, pack2(xlnw[w][ff]), *(const unsigned long long*)&W2s[ff*OO + 2*lane]);
        *(unsigned long long*)(xpb + (size_t)s*OO + 2*lane) = acc;
        __syncwarp();
    }
}

// ---------------- K5: P_m = projK @ projQ^T ----------------
__global__ void k_pgemm(const float* __restrict__ proj) {
    int bm = blockIdx.z;
    int b = bm >> 2, m = bm & 3;
    const float* A  = proj + ((size_t)(b*IN_N + 2*m    )*SS)*FF;
    const float* Bm = proj + ((size_t)(b*IN_N + 2*m + 1)*SS)*FF;
    float*       Cm = g_P + (size_t)bm*SS*SS;
    int m0 = blockIdx.y * 64, n0 = blockIdx.x * 64;

    __shared__ float As[16][64];
    __shared__ float Bs[16][64];
    int tid = threadIdx.x;
    int lr  = tid >> 2;
    int lc  = (tid & 3) * 4;
    int ty  = tid >> 4, tx = tid & 15;

    unsigned long long acc[4][2];
#pragma unroll
    for (int r = 0; r < 4; r++) { acc[r][0] = 0ull; acc[r][1] = 0ull; }

    for (int k0 = 0; k0 < FF; k0 += 16) {
        int row = m0 + lr;
        float4 va = (row < SS) ? *(const float4*)(A + (size_t)row*FF + k0 + lc)
                               : make_float4(0,0,0,0);
        As[lc+0][lr] = va.x; As[lc+1][lr] = va.y; As[lc+2][lr] = va.z; As[lc+3][lr] = va.w;
        int rowb = n0 + lr;
        float4 vb = (rowb < SS) ? *(const float4*)(Bm + (size_t)rowb*FF + k0 + lc)
                                : make_float4(0,0,0,0);
        Bs[lc+0][lr] = vb.x; Bs[lc+1][lr] = vb.y; Bs[lc+2][lr] = vb.z; Bs[lc+3][lr] = vb.w;
        __syncthreads();
#pragma unroll
        for (int k = 0; k < 16; k++) {
            float4 a4 = *(const float4*)&As[k][ty*4];
            ulonglong2 b2 = *(const ulonglong2*)&Bs[k][tx*4];
            unsigned long long p0 = pack2(a4.x), p1 = pack2(a4.y);
            unsigned long long p2 = pack2(a4.z), p3 = pack2(a4.w);
            ffma2(acc[0][0], p0, b2.x); ffma2(acc[0][1], p0, b2.y);
            ffma2(acc[1][0], p1, b2.x); ffma2(acc[1][1], p1, b2.y);
            ffma2(acc[2][0], p2, b2.x); ffma2(acc[2][1], p2, b2.y);
            ffma2(acc[3][0], p3, b2.x); ffma2(acc[3][1], p3, b2.y);
        }
        __syncthreads();
    }
#pragma unroll
    for (int r = 0; r < 4; r++) {
        int sRow = m0 + ty*4 + r;
        if (sRow >= SS) continue;
        float c0, c1, c2, c3;
        unpack2(acc[r][0], c0, c1);
        unpack2(acc[r][1], c2, c3);
        int tCol = n0 + tx*4;
        float* dst = Cm + (size_t)sRow*SS + tCol;
        if (tCol + 3 < SS) { dst[0]=c0; dst[1]=c1; dst[2]=c2; dst[3]=c3; }
        else {
            if (tCol+0 < SS) dst[0]=c0;
            if (tCol+1 < SS) dst[1]=c1;
            if (tCol+2 < SS) dst[2]=c2;
            if (tCol+3 < SS) dst[3]=c3;
        }
    }
}

// ---------------- K6: fused raw-reconstruct + softmax + attn GEMM + conv + residual ----
#define AST_LD 65
__global__ void k_attn(const float* __restrict__ w3,
                       const float* __restrict__ alpha,
                       const float* __restrict__ beta,
                       const float* __restrict__ theta,
                       const float* __restrict__ gamma,
                       const float* __restrict__ temp,
                       float* __restrict__ outp) {
    extern __shared__ float smem[];
    float* Ast = smem;                   // 192*65
    float* Bxs = Ast + 192*AST_LD;       // 192*64
    float* w3s = Bxs + 192*64;           // 960
    __shared__ float qr_sh[SS], qmr_sh[SS];
    __shared__ float km_sh[64], As_sh[64];
    __shared__ float a_sh[4];

    int bj = blockIdx.y;
    int j  = bj & 7, b = bj >> 3;
    int m0 = blockIdx.x * 64;
    int tid = threadIdx.x;

    const float* Bx = g_xp  + (size_t)bj*SS*OO;
    const float* Cb = g_comb + (size_t)bj*SS*FF;
    float*       Ob = outp + (size_t)bj*SS*OO;

    float tv = fabsf(temp[0]) * sqrtf((float)SS / 256.0f) + 1e-4f;
    float inv_scale = 1.0f / (16.0f * tv);

    for (int t = tid; t < SS*OO/4; t += 256)
        ((float4*)Bxs)[t] = ((const float4*)Bx)[t];
    for (int t = SS*OO + tid; t < 192*64; t += 256) Bxs[t] = 0.f;
    for (int t = tid; t < OO*KK; t += 256) w3s[t] = w3[(size_t)j*OO*KK + t];

    if (tid < 4) {
        float gK = g_gate[(b*IN_N + 2*tid    )*JJ + j];
        float gQ = g_gate[(b*IN_N + 2*tid + 1)*JJ + j];
        a_sh[tid] = gK * gQ;
    }
    if (tid < SS) {
        float qm = 0.f, qs = 0.f;
#pragma unroll
        for (int m = 0; m < 4; m++) {
            int bi = b*IN_N + 2*m + 1;
            float g = g_gate[bi*JJ + j];
            qm += g * g_rs[bi*SS + tid];
            qs += g * g * g_ss[bi*SS + tid];
        }
        qm *= (1.0f/256.0f); qs *= (1.0f/256.0f);
        float qr = rsqrtf(qs - qm*qm + 1e-5f);
        qr_sh[tid]  = qr;
        qmr_sh[tid] = 256.0f * qm * qr;
    }
    if (tid >= 192) {
        int r = tid - 192;
        int s = m0 + r;
        if (s < SS) {
            float km = 0.f, ks = 0.f;
#pragma unroll
            for (int m = 0; m < 4; m++) {
                int bi = b*IN_N + 2*m;
                float g = g_gate[bi*JJ + j];
                km += g * g_rs[bi*SS + s];
                ks += g * g * g_ss[bi*SS + s];
            }
            km *= (1.0f/256.0f); ks *= (1.0f/256.0f);
            float kr = rsqrtf(ks - km*km + 1e-5f);
            km_sh[r] = km;
            As_sh[r] = inv_scale * kr;
        }
    }
    __syncthreads();

    float a0 = a_sh[0], a1 = a_sh[1], a2 = a_sh[2], a3 = a_sh[3];
    const float* Pb = g_P + (size_t)(b*4)*SS*SS;

    int w = tid >> 5, lane = tid & 31;
    for (int r = w; r < 64; r += 8) {
        int s = m0 + r;
        if (s < SS) {
            float km = km_sh[r], Asc = As_sh[r];
            const float* P0 = Pb + (size_t)0*SS*SS + (size_t)s*SS;
            const float* P1 = Pb + (size_t)1*SS*SS + (size_t)s*SS;
            const float* P2 = Pb + (size_t)2*SS*SS + (size_t)s*SS;
            const float* P3 = Pb + (size_t)3*SS*SS + (size_t)s*SS;
            float v[6];
            float mx = -3.0e38f;
#pragma unroll
            for (int u = 0; u < 6; u++) {
                int t = lane + 32*u;
                if (t < SS) {
                    float G = a0*P0[t] + a1*P1[t] + a2*P2[t] + a3*P3[t];
                    v[u] = Asc * (qr_sh[t]*G - km*qmr_sh[t]);
                } else v[u] = -3.0e38f;
                mx = fmaxf(mx, v[u]);
            }
#pragma unroll
            for (int o = 16; o > 0; o >>= 1) mx = fmaxf(mx, __shfl_xor_sync(0xffffffffu, mx, o));
            float sum = 0.f;
#pragma unroll
            for (int u = 0; u < 6; u++) {
                int t = lane + 32*u;
                v[u] = (t < SS) ? expf(v[u] - mx) : 0.f;
                sum += v[u];
            }
#pragma unroll
            for (int o = 16; o > 0; o >>= 1) sum += __shfl_xor_sync(0xffffffffu, sum, o);
            float inv = 1.0f / sum;
#pragma unroll
            for (int u = 0; u < 6; u++) Ast[(lane + 32*u)*AST_LD + r] = v[u] * inv;
        } else {
#pragma unroll
            for (int u = 0; u < 6; u++) Ast[(lane + 32*u)*AST_LD + r] = 0.f;
        }
    }
    __syncthreads();

    int ty = tid >> 4, tx = tid & 15;
    unsigned long long acc[4][2];
#pragma unroll
    for (int r = 0; r < 4; r++) { acc[r][0] = 0ull; acc[r][1] = 0ull; }

#pragma unroll 4
    for (int k = 0; k < 192; k++) {
        const float* ap = Ast + k*AST_LD + ty*4;
        float b0 = ap[0], b1 = ap[1], b2v = ap[2], b3 = ap[3];
        ulonglong2 bp = *(const ulonglong2*)(Bxs + k*64 + tx*4);
        unsigned long long p0 = pack2(b0), p1 = pack2(b1);
        unsigned long long p2 = pack2(b2v), p3 = pack2(b3);
        ffma2(acc[0][0], p0, bp.x); ffma2(acc[0][1], p0, bp.y);
        ffma2(acc[1][0], p1, bp.x); ffma2(acc[1][1], p1, bp.y);
        ffma2(acc[2][0], p2, bp.x); ffma2(acc[2][1], p2, bp.y);
        ffma2(acc[3][0], p3, bp.x); ffma2(acc[3][1], p3, bp.y);
    }

    float al = fabsf(alpha[j]), be = fabsf(beta[j]);
    float th = fabsf(theta[j]), ga = gamma[j];

#pragma unroll
    for (int r = 0; r < 4; r++) {
        int s = m0 + ty*4 + r;
        if (s >= SS) continue;
        float cv4[4];
        unpack2(acc[r][0], cv4[0], cv4[1]);
        unpack2(acc[r][1], cv4[2], cv4[3]);
#pragma unroll
        for (int c = 0; c < 4; c++) {
            int o = tx*4 + c;
            float cv = 0.f;
#pragma unroll
            for (int k = 0; k < KK; k++) {
                int si = s + k - 7;
                if (si >= 0 && si < SS) cv += Bxs[si*64 + o] * w3s[o*KK + k];
            }
            float xpv = Bxs[s*64 + o];
            Ob[(size_t)s*OO + o] = be*cv4[c] + al*xpv + th*cv + ga*Cb[(size_t)s*FF + o];
        }
    }
}

// ---------------- launch ----------------
extern "C" void kernel_launch(void* const* d_in, const int* in_sizes, int n_in,
                              void* d_out, int out_size) {
    const float* x_in   = (const float*)d_in[0];
    const float* proj   = (const float*)d_in[1];
    const float* sw     = (const float*)d_in[2];
    const float* tau    = (const float*)d_in[3];
    const float* temp   = (const float*)d_in[4];
    const float* omiga  = (const float*)d_in[5];
    const float* W2     = (const float*)d_in[6];
    const float* bparam = (const float*)d_in[7];
    const float* lnsc   = (const float*)d_in[8];
    const float* lnbi   = (const float*)d_in[9];
    const float* alpha  = (const float*)d_in[10];
    const float* beta   = (const float*)d_in[11];
    const float* theta  = (const float*)d_in[12];
    const float* gamma  = (const float*)d_in[13];
    const float* w3     = (const float*)d_in[14];
    float* outp = (float*)d_out;

    const int attn_smem = (192*AST_LD + 192*64 + OO*KK) * sizeof(float);
    cudaFuncSetAttribute(k_attn, cudaFuncAttributeMaxDynamicSharedMemorySize, attn_smem);

    k_prep    <<<148 + BB*IN_N, 256>>>(x_in, BB*IN_N*SS*FF, proj);
    k_spline  <<<dim3(BB*IN_N, 8), 256>>>(x_in, sw, omiga);
    k_pgemm   <<<dim3(3, 3, BB*4), 256>>>(proj);
    k_combined<<<dim3(BB*JJ, 8), 256>>>(tau, temp);
    k_xp      <<<dim3(BB*JJ, 4), 256>>>(W2, bparam, lnsc, lnbi);
    k_attn    <<<dim3(3, BB*JJ), 256, attn_smem>>>(w3, alpha, beta, theta, gamma, temp, outp);

    if (out_size >= 2 * NOUT) {
        void* xp_dev = nullptr;
        cudaGetSymbolAddress(&xp_dev, g_xp);
        cudaMemcpyAsync((float*)d_out + NOUT, xp_dev, (size_t)NOUT * sizeof(float),
                        cudaMemcpyDeviceToDevice);
    }
}

// round 6
// speedup vs baseline: 2.8619x; 1.0158x over previous
#include <cuda_runtime.h>
#include <cuda_fp16.h>
#include <math.h>

#define BB 8
#define IN_N 8
#define JJ 8
#define SS 187
#define FF 64
#define OO 64
#define CC 67
#define KK 15
#define SF (SS*FF)
#define NOUT (BB*JJ*SS*OO)
#define ECHUNK 1496    // SF/8

// ---------------- device scratch ----------------
__device__ float  g_pmax[148];
__device__ float  g_epart[BB*IN_N*8*JJ];
__device__ float  g_gate[BB*IN_N*JJ];
__device__ __half g_act [BB*IN_N*JJ*SF];   // 12.3 MB (fp16)
__device__ float  g_comb[BB*JJ*SS*FF];
__device__ float  g_xp  [BB*JJ*SS*OO];
__device__ float  g_rs  [BB*IN_N*SS];
__device__ float  g_ss  [BB*IN_N*SS];
__device__ float  g_P   [BB*4*SS*SS];

// ---------------- f32x2 helpers ----------------
__device__ __forceinline__ unsigned long long pack2(float a) {
    unsigned long long r;
    asm("mov.b64 %0, {%1, %1};" : "=l"(r) : "f"(a));
    return r;
}
__device__ __forceinline__ void ffma2(unsigned long long& d, unsigned long long a,
                                      unsigned long long b) {
    asm("fma.rn.f32x2 %0, %1, %2, %0;" : "+l"(d) : "l"(a), "l"(b));
}
__device__ __forceinline__ void unpack2(unsigned long long v, float& lo, float& hi) {
    asm("mov.b64 {%0, %1}, %2;" : "=f"(lo), "=f"(hi) : "l"(v));
}

// ---------------- K1: fused maxabs partials + proj row stats ----------------
__global__ void k_prep(const float* __restrict__ x, int n, const float* __restrict__ proj) {
    if (blockIdx.x < 148) {
        __shared__ float sred[256];
        float m = 0.f;
        for (int i = blockIdx.x * 256 + threadIdx.x; i < n; i += 148 * 256)
            m = fmaxf(m, fabsf(x[i]));
        sred[threadIdx.x] = m;
        __syncthreads();
        for (int st = 128; st > 0; st >>= 1) {
            if (threadIdx.x < st) sred[threadIdx.x] = fmaxf(sred[threadIdx.x], sred[threadIdx.x + st]);
            __syncthreads();
        }
        if (threadIdx.x == 0) g_pmax[blockIdx.x] = sred[0];
    } else {
        int bi = blockIdx.x - 148;
        int w = threadIdx.x >> 5, lane = threadIdx.x & 31;
        const float* pb = proj + (size_t)bi*SS*FF;
        for (int s = w; s < SS; s += 8) {
            float a = pb[(size_t)s*FF + lane];
            float c = pb[(size_t)s*FF + lane + 32];
            float sm = a + c, sq = a*a + c*c;
#pragma unroll
            for (int o = 16; o > 0; o >>= 1) {
                sm += __shfl_xor_sync(0xffffffffu, sm, o);
                sq += __shfl_xor_sync(0xffffffffu, sq, o);
            }
            if (lane == 0) { g_rs[bi*SS + s] = sm; g_ss[bi*SS + s] = sq; }
        }
    }
}

__device__ __forceinline__ float reduce_maxv(int tid, float* s_pm) {
    if (tid < 32) {
        float m = 0.f;
        for (int t = tid; t < 148; t += 32) m = fmaxf(m, g_pmax[t]);
#pragma unroll
        for (int o = 16; o > 0; o >>= 1) m = fmaxf(m, __shfl_xor_sync(0xffffffffu, m, o));
        if (tid == 0) *s_pm = m;
    }
    __syncthreads();
    return *s_pm;
}

__device__ __forceinline__ void spline_basis(float x, float inv_maxv_sc, float invh,
                                             float bas[4], int& c0) {
    float xn = x * inv_maxv_sc;
    xn = fminf(fmaxf(xn, -0.99f), 0.99f);
    float u = (xn + 1.0f) * invh;
    float fl = floorf(u);
    float t = u - fl;
    int fli = (int)fl;
    c0 = fli - 1;
    float omt = 1.0f - t;
    float t3 = t*t*t;
    float o3 = omt*omt*omt;
    float b0 = o3 * (1.0f/6.0f);
    float b1 = (2.0f-t)*(2.0f-t)*(2.0f-t)*(1.0f/6.0f) - o3*(4.0f/6.0f);
    float b2 = (1.0f+t)*(1.0f+t)*(1.0f+t)*(1.0f/6.0f) - t3*(4.0f/6.0f);
    float b3 = t3 * (1.0f/6.0f);
    bas[0] = (fli >= 1)  ? b0 : 0.f;
    bas[1] = b1;
    bas[2] = b2;
    bas[3] = (fli <= 64) ? b3 : 0.f;
}

// ---------------- K2: spline -> activated(fp16) + energy partials ----------------
__global__ void k_spline(const float* __restrict__ x_in,
                         const float* __restrict__ sw,
                         const float* __restrict__ omiga) {
    int bi = blockIdx.x, i = bi % IN_N, cy = blockIdx.y;
    __shared__ float s_sw[JJ*CC];
    __shared__ float s_om[JJ];
    __shared__ float s_red[8][9];
    __shared__ float s_pm;
    int tid = threadIdx.x;
    float maxv = reduce_maxv(tid, &s_pm) + 1e-8f;
    for (int t = tid; t < JJ*CC; t += blockDim.x) s_sw[t] = sw[i*JJ*CC + t];
    if (tid < JJ) s_om[tid] = fabsf(omiga[i*JJ + tid]);
    __syncthreads();

    float inv_maxv_sc = 0.95f / maxv;
    const float invh = (float)(CC - 1) * 0.5f;
    float acc[JJ];
#pragma unroll
    for (int j = 0; j < JJ; j++) acc[j] = 0.f;

    const float* xb   = x_in + (size_t)bi * SF;
    __half*      actb = g_act + (size_t)bi * JJ * SF;
    int start = cy * ECHUNK, end = min(SF, start + ECHUNK);
    for (int idx = start + tid; idx < end; idx += blockDim.x) {
        float x = xb[idx];
        float bas[4]; int c0;
        spline_basis(x, inv_maxv_sc, invh, bas, c0);
        int i0 = max(c0, 0);
        int i3 = min(c0 + 3, CC - 1);
#pragma unroll
        for (int j = 0; j < JJ; j++) {
            const float* swj = s_sw + j*CC;
            float a = bas[0]*swj[i0] + bas[1]*swj[c0+1] + bas[2]*swj[c0+2]
                    + bas[3]*swj[i3] + s_om[j] * x;
            actb[(size_t)j*SF + idx] = __float2half_rn(a);
            acc[j] += a * a;
        }
    }
    int lane = tid & 31, wid = tid >> 5;
#pragma unroll
    for (int j = 0; j < JJ; j++) {
#pragma unroll
        for (int o = 16; o > 0; o >>= 1) acc[j] += __shfl_down_sync(0xffffffffu, acc[j], o);
        if (lane == 0) s_red[wid][j] = acc[j];
    }
    __syncthreads();
    if (tid < JJ) {
        float e = 0.f;
#pragma unroll
        for (int w = 0; w < 8; w++) e += s_red[w][tid];
        g_epart[(bi*8 + cy)*JJ + tid] = e;
    }
}

// ---------------- K3: fused combined + LN + W2 GEMV ----------------
__global__ void k_cxp(const float* __restrict__ W2,
                      const float* __restrict__ bparam,
                      const float* __restrict__ lnsc,
                      const float* __restrict__ lnbi,
                      const float* __restrict__ tau,
                      const float* __restrict__ temp) {
    int bj = blockIdx.x;
    int b = bj >> 3, j = bj & 7;
    __shared__ float W2s[FF*OO];
    __shared__ float s_sc[FF], s_bi[FF];
    __shared__ float s_mask[IN_N];
    __shared__ float xlnw[8][FF];
    int tid = threadIdx.x;

    for (int t = tid; t < FF*OO/4; t += blockDim.x)
        ((float4*)W2s)[t] = ((const float4*)(W2 + (size_t)j*FF*OO))[t];
    if (tid < FF) {
        s_sc[tid] = lnsc[j*FF + tid];
        s_bi[tid] = lnbi[j*FF + tid];
    }
    if (tid < IN_N) {
        int i = tid;
        int bi = b*IN_N + i;
        float e = 0.f;
#pragma unroll
        for (int c = 0; c < 8; c++) e += g_epart[(bi*8 + c)*JJ + j];
        e *= (1.0f / (float)SF);
        float sq = sqrtf(e + 1e-8f);
        float ta = fabsf(tau[i*JJ + j]);
        float tv = fabsf(temp[0]) * sqrtf((float)SS / 256.0f) + 1e-4f;
        float mk = 1.0f / (1.0f + expf(-(sq - ta) / tv));
        s_mask[tid] = mk;
        if (blockIdx.y == 0) g_gate[bi*JJ + j] = (sq / (ta + 1e-8f)) * mk;
    }
    __syncthreads();

    int w = tid >> 5, lane = tid & 31;
    int s0 = blockIdx.y * 24;
    int s1 = min(SS, s0 + 24);
    const float* bpj = bparam + (size_t)j*SS*OO;
    float* cmbb = g_comb + (size_t)bj*SF;
    float* xpb  = g_xp   + (size_t)bj*SS*OO;

    float m[8];
#pragma unroll
    for (int i = 0; i < 8; i++) m[i] = s_mask[i];

    for (int s = s0 + w; s < s1; s += 8) {
        float c0 = 0.f, c1 = 0.f;
#pragma unroll
        for (int i = 0; i < IN_N; i++) {
            const __half2* ap = (const __half2*)(g_act + ((size_t)(b*IN_N + i)*JJ + j)*SF
                                                 + (size_t)s*FF + 2*lane);
            float2 f2 = __half22float2(*ap);
            c0 += m[i] * f2.x;
            c1 += m[i] * f2.y;
        }
        *(float2*)(cmbb + (size_t)s*FF + 2*lane) = make_float2(c0, c1);

        float sm = c0 + c1, sq = c0*c0 + c1*c1;
#pragma unroll
        for (int o = 16; o > 0; o >>= 1) {
            sm += __shfl_xor_sync(0xffffffffu, sm, o);
            sq += __shfl_xor_sync(0xffffffffu, sq, o);
        }
        float mean = sm * (1.0f/64.0f);
        float var  = sq * (1.0f/64.0f) - mean*mean;
        float rstd = rsqrtf(var + 1e-5f);
        xlnw[w][2*lane]     = (c0 - mean)*rstd*s_sc[2*lane]     + s_bi[2*lane];
        xlnw[w][2*lane + 1] = (c1 - mean)*rstd*s_sc[2*lane + 1] + s_bi[2*lane + 1];
        __syncwarp();
        unsigned long long acc = *(const unsigned long long*)(bpj + (size_t)s*OO + 2*lane);
#pragma unroll
        for (int ff = 0; ff < FF; ff++)
            ffma2(acc, pack2(xlnw[w][ff]), *(const unsigned long long*)&W2s[ff*OO + 2*lane]);
        *(unsigned long long*)(xpb + (size_t)s*OO + 2*lane) = acc;
        __syncwarp();
    }
}

// ---------------- K4: P_m = projK @ projQ^T ----------------
__global__ void k_pgemm(const float* __restrict__ proj) {
    int bm = blockIdx.z;
    int b = bm >> 2, m = bm & 3;
    const float* A  = proj + ((size_t)(b*IN_N + 2*m    )*SS)*FF;
    const float* Bm = proj + ((size_t)(b*IN_N + 2*m + 1)*SS)*FF;
    float*       Cm = g_P + (size_t)bm*SS*SS;
    int m0 = blockIdx.y * 64, n0 = blockIdx.x * 64;

    __shared__ float As[16][64];
    __shared__ float Bs[16][64];
    int tid = threadIdx.x;
    int lr  = tid >> 2;
    int lc  = (tid & 3) * 4;
    int ty  = tid >> 4, tx = tid & 15;

    unsigned long long acc[4][2];
#pragma unroll
    for (int r = 0; r < 4; r++) { acc[r][0] = 0ull; acc[r][1] = 0ull; }

    for (int k0 = 0; k0 < FF; k0 += 16) {
        int row = m0 + lr;
        float4 va = (row < SS) ? *(const float4*)(A + (size_t)row*FF + k0 + lc)
                               : make_float4(0,0,0,0);
        As[lc+0][lr] = va.x; As[lc+1][lr] = va.y; As[lc+2][lr] = va.z; As[lc+3][lr] = va.w;
        int rowb = n0 + lr;
        float4 vb = (rowb < SS) ? *(const float4*)(Bm + (size_t)rowb*FF + k0 + lc)
                                : make_float4(0,0,0,0);
        Bs[lc+0][lr] = vb.x; Bs[lc+1][lr] = vb.y; Bs[lc+2][lr] = vb.z; Bs[lc+3][lr] = vb.w;
        __syncthreads();
#pragma unroll
        for (int k = 0; k < 16; k++) {
            float4 a4 = *(const float4*)&As[k][ty*4];
            ulonglong2 b2 = *(const ulonglong2*)&Bs[k][tx*4];
            unsigned long long p0 = pack2(a4.x), p1 = pack2(a4.y);
            unsigned long long p2 = pack2(a4.z), p3 = pack2(a4.w);
            ffma2(acc[0][0], p0, b2.x); ffma2(acc[0][1], p0, b2.y);
            ffma2(acc[1][0], p1, b2.x); ffma2(acc[1][1], p1, b2.y);
            ffma2(acc[2][0], p2, b2.x); ffma2(acc[2][1], p2, b2.y);
            ffma2(acc[3][0], p3, b2.x); ffma2(acc[3][1], p3, b2.y);
        }
        __syncthreads();
    }
#pragma unroll
    for (int r = 0; r < 4; r++) {
        int sRow = m0 + ty*4 + r;
        if (sRow >= SS) continue;
        float c0, c1, c2, c3;
        unpack2(acc[r][0], c0, c1);
        unpack2(acc[r][1], c2, c3);
        int tCol = n0 + tx*4;
        float* dst = Cm + (size_t)sRow*SS + tCol;
        if (tCol + 3 < SS) { dst[0]=c0; dst[1]=c1; dst[2]=c2; dst[3]=c3; }
        else {
            if (tCol+0 < SS) dst[0]=c0;
            if (tCol+1 < SS) dst[1]=c1;
            if (tCol+2 < SS) dst[2]=c2;
            if (tCol+3 < SS) dst[3]=c3;
        }
    }
}

// ---------------- K5: fused raw-reconstruct + softmax + attn GEMM + conv + residual ----
#define AST_LD 65
__global__ void k_attn(const float* __restrict__ w3,
                       const float* __restrict__ alpha,
                       const float* __restrict__ beta,
                       const float* __restrict__ theta,
                       const float* __restrict__ gamma,
                       const float* __restrict__ temp,
                       float* __restrict__ outp) {
    extern __shared__ float smem[];
    float* Ast = smem;
    float* Bxs = Ast + 192*AST_LD;
    float* w3s = Bxs + 192*64;
    __shared__ float qr_sh[SS], qmr_sh[SS];
    __shared__ float km_sh[64], As_sh[64];
    __shared__ float a_sh[4];

    int bj = blockIdx.y;
    int j  = bj & 7, b = bj >> 3;
    int m0 = blockIdx.x * 64;
    int tid = threadIdx.x;

    const float* Bx = g_xp  + (size_t)bj*SS*OO;
    const float* Cb = g_comb + (size_t)bj*SS*FF;
    float*       Ob = outp + (size_t)bj*SS*OO;

    float tv = fabsf(temp[0]) * sqrtf((float)SS / 256.0f) + 1e-4f;
    float inv_scale = 1.0f / (16.0f * tv);

    for (int t = tid; t < SS*OO/4; t += 256)
        ((float4*)Bxs)[t] = ((const float4*)Bx)[t];
    for (int t = SS*OO + tid; t < 192*64; t += 256) Bxs[t] = 0.f;
    for (int t = tid; t < OO*KK; t += 256) w3s[t] = w3[(size_t)j*OO*KK + t];

    if (tid < 4) {
        float gK = g_gate[(b*IN_N + 2*tid    )*JJ + j];
        float gQ = g_gate[(b*IN_N + 2*tid + 1)*JJ + j];
        a_sh[tid] = gK * gQ;
    }
    if (tid < SS) {
        float qm = 0.f, qs = 0.f;
#pragma unroll
        for (int m = 0; m < 4; m++) {
            int bi = b*IN_N + 2*m + 1;
            float g = g_gate[bi*JJ + j];
            qm += g * g_rs[bi*SS + tid];
            qs += g * g * g_ss[bi*SS + tid];
        }
        qm *= (1.0f/256.0f); qs *= (1.0f/256.0f);
        float qr = rsqrtf(qs - qm*qm + 1e-5f);
        qr_sh[tid]  = qr;
        qmr_sh[tid] = 256.0f * qm * qr;
    }
    if (tid >= 192) {
        int r = tid - 192;
        int s = m0 + r;
        if (s < SS) {
            float km = 0.f, ks = 0.f;
#pragma unroll
            for (int m = 0; m < 4; m++) {
                int bi = b*IN_N + 2*m;
                float g = g_gate[bi*JJ + j];
                km += g * g_rs[bi*SS + s];
                ks += g * g * g_ss[bi*SS + s];
            }
            km *= (1.0f/256.0f); ks *= (1.0f/256.0f);
            float kr = rsqrtf(ks - km*km + 1e-5f);
            km_sh[r] = km;
            As_sh[r] = inv_scale * kr;
        }
    }
    __syncthreads();

    float a0 = a_sh[0], a1 = a_sh[1], a2 = a_sh[2], a3 = a_sh[3];
    const float* Pb = g_P + (size_t)(b*4)*SS*SS;

    int w = tid >> 5, lane = tid & 31;
    for (int r = w; r < 64; r += 8) {
        int s = m0 + r;
        if (s < SS) {
            float km = km_sh[r], Asc = As_sh[r];
            const float* P0 = Pb + (size_t)0*SS*SS + (size_t)s*SS;
            const float* P1 = Pb + (size_t)1*SS*SS + (size_t)s*SS;
            const float* P2 = Pb + (size_t)2*SS*SS + (size_t)s*SS;
            const float* P3 = Pb + (size_t)3*SS*SS + (size_t)s*SS;
            float v[6];
            float mx = -3.0e38f;
#pragma unroll
            for (int u = 0; u < 6; u++) {
                int t = lane + 32*u;
                if (t < SS) {
                    float G = a0*P0[t] + a1*P1[t] + a2*P2[t] + a3*P3[t];
                    v[u] = Asc * (qr_sh[t]*G - km*qmr_sh[t]);
                } else v[u] = -3.0e38f;
                mx = fmaxf(mx, v[u]);
            }
#pragma unroll
            for (int o = 16; o > 0; o >>= 1) mx = fmaxf(mx, __shfl_xor_sync(0xffffffffu, mx, o));
            float sum = 0.f;
#pragma unroll
            for (int u = 0; u < 6; u++) {
                int t = lane + 32*u;
                v[u] = (t < SS) ? expf(v[u] - mx) : 0.f;
                sum += v[u];
            }
#pragma unroll
            for (int o = 16; o > 0; o >>= 1) sum += __shfl_xor_sync(0xffffffffu, sum, o);
            float inv = 1.0f / sum;
#pragma unroll
            for (int u = 0; u < 6; u++) Ast[(lane + 32*u)*AST_LD + r] = v[u] * inv;
        } else {
#pragma unroll
            for (int u = 0; u < 6; u++) Ast[(lane + 32*u)*AST_LD + r] = 0.f;
        }
    }
    __syncthreads();

    int ty = tid >> 4, tx = tid & 15;
    unsigned long long acc[4][2];
#pragma unroll
    for (int r = 0; r < 4; r++) { acc[r][0] = 0ull; acc[r][1] = 0ull; }

#pragma unroll 4
    for (int k = 0; k < 192; k++) {
        const float* ap = Ast + k*AST_LD + ty*4;
        float b0 = ap[0], b1 = ap[1], b2v = ap[2], b3 = ap[3];
        ulonglong2 bp = *(const ulonglong2*)(Bxs + k*64 + tx*4);
        unsigned long long p0 = pack2(b0), p1 = pack2(b1);
        unsigned long long p2 = pack2(b2v), p3 = pack2(b3);
        ffma2(acc[0][0], p0, bp.x); ffma2(acc[0][1], p0, bp.y);
        ffma2(acc[1][0], p1, bp.x); ffma2(acc[1][1], p1, bp.y);
        ffma2(acc[2][0], p2, bp.x); ffma2(acc[2][1], p2, bp.y);
        ffma2(acc[3][0], p3, bp.x); ffma2(acc[3][1], p3, bp.y);
    }

    float al = fabsf(alpha[j]), be = fabsf(beta[j]);
    float th = fabsf(theta[j]), ga = gamma[j];

#pragma unroll
    for (int r = 0; r < 4; r++) {
        int s = m0 + ty*4 + r;
        if (s >= SS) continue;
        float cv4[4];
        unpack2(acc[r][0], cv4[0], cv4[1]);
        unpack2(acc[r][1], cv4[2], cv4[3]);
#pragma unroll
        for (int c = 0; c < 4; c++) {
            int o = tx*4 + c;
            float cv = 0.f;
#pragma unroll
            for (int k = 0; k < KK; k++) {
                int si = s + k - 7;
                if (si >= 0 && si < SS) cv += Bxs[si*64 + o] * w3s[o*KK + k];
            }
            float xpv = Bxs[s*64 + o];
            Ob[(size_t)s*OO + o] = be*cv4[c] + al*xpv + th*cv + ga*Cb[(size_t)s*FF + o];
        }
    }
}

// ---------------- launch ----------------
extern "C" void kernel_launch(void* const* d_in, const int* in_sizes, int n_in,
                              void* d_out, int out_size) {
    const float* x_in   = (const float*)d_in[0];
    const float* proj   = (const float*)d_in[1];
    const float* sw     = (const float*)d_in[2];
    const float* tau    = (const float*)d_in[3];
    const float* temp   = (const float*)d_in[4];
    const float* omiga  = (const float*)d_in[5];
    const float* W2     = (const float*)d_in[6];
    const float* bparam = (const float*)d_in[7];
    const float* lnsc   = (const float*)d_in[8];
    const float* lnbi   = (const float*)d_in[9];
    const float* alpha  = (const float*)d_in[10];
    const float* beta   = (const float*)d_in[11];
    const float* theta  = (const float*)d_in[12];
    const float* gamma  = (const float*)d_in[13];
    const float* w3     = (const float*)d_in[14];
    float* outp = (float*)d_out;

    static cudaStream_t s2 = nullptr;
    static cudaEvent_t evA = nullptr, evB = nullptr;
    if (!s2) {
        cudaStreamCreateWithFlags(&s2, cudaStreamNonBlocking);
        cudaEventCreateWithFlags(&evA, cudaEventDisableTiming);
        cudaEventCreateWithFlags(&evB, cudaEventDisableTiming);
    }

    const int attn_smem = (192*AST_LD + 192*64 + OO*KK) * sizeof(float);
    cudaFuncSetAttribute(k_attn, cudaFuncAttributeMaxDynamicSharedMemorySize, attn_smem);

    // fork: pgemm depends only on proj
    cudaEventRecord(evA, 0);
    cudaStreamWaitEvent(s2, evA, 0);
    k_pgemm<<<dim3(3, 3, BB*4), 256, 0, s2>>>(proj);
    cudaEventRecord(evB, s2);

    k_prep  <<<148 + BB*IN_N, 256>>>(x_in, BB*IN_N*SS*FF, proj);
    k_spline<<<dim3(BB*IN_N, 8), 256>>>(x_in, sw, omiga);
    k_cxp   <<<dim3(BB*JJ, 8), 256>>>(W2, bparam, lnsc, lnbi, tau, temp);

    // join before attn (needs g_P)
    cudaStreamWaitEvent(0, evB, 0);
    k_attn  <<<dim3(3, BB*JJ), 256, attn_smem>>>(w3, alpha, beta, theta, gamma, temp, outp);

    if (out_size >= 2 * NOUT) {
        void* xp_dev = nullptr;
        cudaGetSymbolAddress(&xp_dev, g_xp);
        cudaMemcpyAsync((float*)d_out + NOUT, xp_dev, (size_t)NOUT * sizeof(float),
                        cudaMemcpyDeviceToDevice);
    }
}